// round 13
// baseline (speedup 1.0000x reference)
#include <cuda_runtime.h>
#include <cuda_fp16.h>
#include <math.h>
#include <stdint.h>

#define HDIM 128
#define MAXN 50000
#define MAXE 640000
#define TMR  128                    // rows per CTA tile

// byte-offset shared layout
#define APB     528                 // A row pitch bytes (264 halves)
#define WB_B    (TMR * APB)         // 67584
#define WB_CHB  16384               // one 64k x 128n fp16 chunk, frag-ordered
#define B1_B    (WB_B + 2 * WB_CHB) // 100352
#define B2_B    (B1_B + 512)
#define W1L_B   (B2_B + 512)
#define DIST_B  (W1L_B + 512)
#define REC_B   (DIST_B + 512)
#define SEND_B  (REC_B + 512)
#define SMEM_BYTES (SEND_B + 512)   // 103424 -> 2 CTAs/SM

// ------------------------- device scratch -------------------------
__device__ __align__(16) float  g_aggr[(size_t)MAXN * HDIM];
__device__ __align__(16) __half g_x16[(size_t)MAXN * HDIM];
__device__ int   g_send[MAXE];
__device__ int   g_rec[MAXE];
__device__ float g_dist[MAXE];
// frag-ordered fp16 weights: [kchunk64][nb*4+ks][lane][reg] packed as halves
__device__ __align__(16) __half g_w1h[4 * 8192];   // edge w1, K=256
__device__ __align__(16) __half g_w2h[2 * 8192];   // edge w2, K=128
__device__ __align__(16) __half g_u1h[4 * 8192];   // node w1, K=256
__device__ __align__(16) __half g_u2h[2 * 8192];   // node w2, K=128

// ------------------------- helpers -------------------------
__device__ __forceinline__ float silu_f(float v) {
    return __fdividef(v, 1.0f + __expf(-v));
}
__device__ __forceinline__ uint32_t cvta_sh(const void* p) {
    uint32_t a;
    asm("{ .reg .u64 t; cvta.to.shared.u64 t, %1; cvt.u32.u64 %0, t; }"
        : "=r"(a) : "l"(p));
    return a;
}
__device__ __forceinline__ void mma16(float d[4], const uint32_t a[4],
                                      const uint32_t b[2]) {
    asm volatile(
        "mma.sync.aligned.m16n8k16.row.col.f32.f16.f16.f32 "
        "{%0,%1,%2,%3},{%4,%5,%6,%7},{%8,%9},{%0,%1,%2,%3};"
        : "+f"(d[0]), "+f"(d[1]), "+f"(d[2]), "+f"(d[3])
        : "r"(a[0]), "r"(a[1]), "r"(a[2]), "r"(a[3]), "r"(b[0]), "r"(b[1]));
}
__device__ __forceinline__ void ldsm4(uint32_t r[4], uint32_t addr) {
    asm volatile("ldmatrix.sync.aligned.m8n8.x4.shared.b16 {%0,%1,%2,%3}, [%4];"
                 : "=r"(r[0]), "=r"(r[1]), "=r"(r[2]), "=r"(r[3]) : "r"(addr));
}
__device__ __forceinline__ void red4(float* p, float a, float b, float c, float d) {
    asm volatile("red.global.add.v4.f32 [%0], {%1,%2,%3,%4};"
                 :: "l"(p), "f"(a), "f"(b), "f"(c), "f"(d) : "memory");
}
__device__ __forceinline__ void cp16(uint32_t dst_sh, const void* src) {
    asm volatile("cp.async.ca.shared.global [%0], [%1], 16;"
                 :: "r"(dst_sh), "l"(src) : "memory");
}
__device__ __forceinline__ void cp_commit() {
    asm volatile("cp.async.commit_group;" ::: "memory");
}
template <int W>
__device__ __forceinline__ void cp_wait() {
    asm volatile("cp.async.wait_group %0;" :: "n"(W) : "memory");
}

// frag-order half-index for weight element (n, k), 64k-chunks.
// word = chunkbase + (nb*4+ks)*64 + lane*2 + reg
__device__ __forceinline__ int fragh(int n, int k) {
    int kc   = k >> 6;
    int ks   = (k >> 4) & 3;
    int reg  = (k >> 3) & 1;
    int lane = (n & 7) * 4 + ((k >> 1) & 3);
    int idx32 = kc * 4096 + (((n >> 3) * 4 + ks) << 6) + lane * 2 + reg;
    return idx32 * 2 + (k & 1);
}

// ------------------------- fused prep kernel -------------------------
__global__ void prep_all(const int* __restrict__ ei32,
                         const float* __restrict__ pos,
                         const float* __restrict__ x,
                         const float* __restrict__ mw1, const float* __restrict__ mw2,
                         const float* __restrict__ uw1, const float* __restrict__ uw2,
                         int N, int E) {
    bool is64 = true;
#pragma unroll
    for (int t = 0; t < 16; t++) is64 &= (ei32[2 * t + 1] == 0);

    const long long NH = (long long)N * HDIM;
    const long long t0 = NH;                 // zero aggr
    const long long t1 = t0 + NH;            // x -> fp16
    const long long t2 = t1 + E;             // edges
    const long long t3 = t2 + 32768;         // edge w1
    const long long t4 = t3 + 16384;         // edge w2
    const long long t5 = t4 + 32768;         // node w1
    const long long t6 = t5 + 16384;         // node w2

    long long i = (long long)blockIdx.x * blockDim.x + threadIdx.x;
    long long st = (long long)gridDim.x * blockDim.x;
    for (; i < t6; i += st) {
        if (i < t0) {
            g_aggr[i] = 0.0f;
        } else if (i < t1) {
            long long j = i - t0;
            g_x16[j] = __float2half_rn(x[j]);
        } else if (i < t2) {
            int e = (int)(i - t1);
            int s, r;
            if (is64) { s = ei32[2 * (size_t)e]; r = ei32[2 * ((size_t)E + e)]; }
            else      { s = ei32[e];             r = ei32[(size_t)E + e]; }
            s = min(max(s, 0), N - 1);
            r = min(max(r, 0), N - 1);
            g_send[e] = s;
            g_rec[e]  = r;
            float dx = pos[s * 3 + 0] - pos[r * 3 + 0];
            float dy = pos[s * 3 + 1] - pos[r * 3 + 1];
            float dz = pos[s * 3 + 2] - pos[r * 3 + 2];
            g_dist[e] = sqrtf(dx * dx + dy * dy + dz * dz);
        } else if (i < t3) {
            int j = (int)(i - t2);
            int n = j >> 8, k = j & 255;
            g_w1h[fragh(n, k)] = __float2half_rn(mw1[k * 128 + n]);
        } else if (i < t4) {
            int j = (int)(i - t3);
            int n = j >> 7, k = j & 127;
            g_w2h[fragh(n, k)] = __float2half_rn(mw2[k * 128 + n]);
        } else if (i < t5) {
            int j = (int)(i - t4);
            int n = j >> 8, k = j & 255;
            g_u1h[fragh(n, k)] = __float2half_rn(uw1[k * 128 + n]);
        } else {
            int j = (int)(i - t5);
            int n = j >> 7, k = j & 127;
            g_u2h[fragh(n, k)] = __float2half_rn(uw2[k * 128 + n]);
        }
    }
}

// ------------------------- fp16 mma GEMMs (32x64 warp tiles, 8 warps) --------
__device__ __forceinline__ void issueB1(const __half* __restrict__ gB, int c,
                                        int buf, uint32_t smbase, int tid) {
#pragma unroll
    for (int it = 0; it < 4; it++) {
        int idx = (tid + it * 256) * 16;
        cp16(smbase + WB_B + buf * WB_CHB + idx, (const char*)gB + c * WB_CHB + idx);
    }
}
__device__ __forceinline__ void issueW2(const __half* __restrict__ gB,
                                        uint32_t smbase, int tid) {
#pragma unroll
    for (int it = 0; it < 8; it++) {
        int idx = (tid + it * 256) * 16;
        cp16(smbase + WB_B + idx, (const char*)gB + idx);
    }
}

// per-thread ldmatrix A base row address (mf=0), koff folded in
__device__ __forceinline__ uint32_t a_addr(uint32_t smbase, int mw, int lane) {
    int row  = mw * 32 + (lane & 7) + ((lane >> 3) & 1) * 8;
    int koff = (lane >> 4) * 8;           // halves
    return smbase + row * APB + koff * 2;
}

// Single barrier per chunk; chunk 0 + gather already in flight (committed by
// caller). Caller must __syncthreads() after return before mutating sA or WB.
__device__ __forceinline__ void gemm1(const __half* __restrict__ gB,
                                      char* smc, uint32_t smbase,
                                      int mw, int nw, int lane, int tid,
                                      float acc[2][8][4]) {
    const uint32_t abase = a_addr(smbase, mw, lane);
    for (int c = 0; c < 4; c++) {
        cp_wait<0>();
        __syncthreads();   // chunk c (+ gather at c=0) visible to all
        if (c + 1 < 4) {
            issueB1(gB, c + 1, (c + 1) & 1, smbase, tid);
            cp_commit();
        }
        const char* wb = smc + WB_B + (c & 1) * WB_CHB;
#pragma unroll
        for (int ks = 0; ks < 4; ks++) {
            uint32_t a[2][4];
            uint2    b[8];
#pragma unroll
            for (int mf = 0; mf < 2; mf++)
                ldsm4(a[mf], abase + mf * 16 * APB + (c * 64 + ks * 16) * 2);
#pragma unroll
            for (int nf = 0; nf < 8; nf++) {
                int nb = nw * 8 + nf;
                b[nf] = *(const uint2*)(wb + (((nb * 4 + ks) << 5) + lane) * 8);
            }
#pragma unroll
            for (int mf = 0; mf < 2; mf++)
#pragma unroll
                for (int nf = 0; nf < 8; nf++)
                    mma16(acc[mf][nf], a[mf], (const uint32_t*)&b[nf]);
        }
    }
}

// GEMM2: whole K=128 in one 32KB frag buffer, no internal barriers
__device__ __forceinline__ void gemm2(char* smc, uint32_t smbase,
                                      int mw, int nw, int lane,
                                      float acc[2][8][4]) {
    const uint32_t abase = a_addr(smbase, mw, lane);
#pragma unroll
    for (int ks8 = 0; ks8 < 8; ks8++) {
        const char* wb = smc + WB_B + (ks8 >> 2) * WB_CHB;
        int ks = ks8 & 3;
        uint32_t a[2][4];
        uint2    b[8];
#pragma unroll
        for (int mf = 0; mf < 2; mf++)
            ldsm4(a[mf], abase + mf * 16 * APB + (ks8 * 16) * 2);
#pragma unroll
        for (int nf = 0; nf < 8; nf++) {
            int nb = nw * 8 + nf;
            b[nf] = *(const uint2*)(wb + (((nb * 4 + ks) << 5) + lane) * 8);
        }
#pragma unroll
        for (int mf = 0; mf < 2; mf++)
#pragma unroll
            for (int nf = 0; nf < 8; nf++)
                mma16(acc[mf][nf], a[mf], (const uint32_t*)&b[nf]);
    }
}

// ------------------------- fused MLP kernel (edge / node) -------------------------
template <bool EDGE>
__global__ void __launch_bounds__(256, 2) mlp_mma_kernel(
    const float* __restrict__ w1full,   // original w1 (dist row, edge only)
    const float* __restrict__ b1, const float* __restrict__ b2,
    float* __restrict__ out, int M) {
    extern __shared__ char smc[];
    const uint32_t smbase = cvta_sh(smc);
    float* sB1  = (float*)(smc + B1_B);
    float* sB2  = (float*)(smc + B2_B);
    float* sW1l = (float*)(smc + W1L_B);
    float* sDst = (float*)(smc + DIST_B);
    int*   sRec = (int*)(smc + REC_B);
    int*   sSnd = (int*)(smc + SEND_B);

    const __half* gw1 = EDGE ? g_w1h : g_u1h;
    const __half* gw2 = EDGE ? g_w2h : g_u2h;

    const int tid  = threadIdx.x;
    const int lane = tid & 31;
    const int wid  = tid >> 5;
    const int mw   = wid >> 1;   // 0..3 (32-row block)
    const int nw   = wid & 1;    // 0..1 (64-col block)
    const int m0   = blockIdx.x * TMR;

    // w1 chunk 0 into flight immediately — overlaps everything below
    issueB1(gw1, 0, 0, smbase, tid);

    if (tid < 128) {
        sB1[tid] = b1[tid];
        sB2[tid] = b2[tid];
        if (EDGE) {
            sW1l[tid] = w1full[(size_t)256 * 128 + tid];
            int ge = m0 + tid;
            if (ge < M) {
                sSnd[tid] = g_send[ge];
                sRec[tid] = g_rec[ge];
                sDst[tid] = g_dist[ge];
            } else {
                sSnd[tid] = 0; sRec[tid] = -1; sDst[tid] = 0.0f;
            }
        }
    }
    __syncthreads();

    // gather state rows: cols 0..127 from x16; 128..255 from x16 (edge) or
    // aggr fp32->fp16 (node). Edge path is pure cp.async (no reg roundtrip).
    const char* x16c = (const char*)g_x16;    // 16B per 8-half group
    for (int i = tid; i < TMR * 16; i += 256) {
        int r = i >> 4, c = i & 15;
        if (EDGE) {
            int s  = sSnd[r];
            int rc = sRec[r];
            if (rc < 0) rc = 0;
            cp16(smbase + r * APB + c * 16,       x16c + ((size_t)s * 16 + c) * 16);
            cp16(smbase + r * APB + 256 + c * 16, x16c + ((size_t)rc * 16 + c) * 16);
        } else {
            int gn = m0 + r;
            if (gn >= M) gn = M - 1;
            cp16(smbase + r * APB + c * 16, x16c + ((size_t)gn * 16 + c) * 16);
            const float4* ar = (const float4*)&g_aggr[(size_t)gn * HDIM + c * 8];
            float4 a0 = ar[0], a1 = ar[1];
            uint4 u;
            ((half2*)&u)[0] = __floats2half2_rn(a0.x, a0.y);
            ((half2*)&u)[1] = __floats2half2_rn(a0.z, a0.w);
            ((half2*)&u)[2] = __floats2half2_rn(a1.x, a1.y);
            ((half2*)&u)[3] = __floats2half2_rn(a1.z, a1.w);
            *(uint4*)(smc + r * APB + 256 + c * 16) = u;
        }
    }
    cp_commit();   // chunk0 + gather cp's in one group

    float acc[2][8][4];
#pragma unroll
    for (int mf = 0; mf < 2; mf++)
#pragma unroll
        for (int nf = 0; nf < 8; nf++)
#pragma unroll
            for (int g = 0; g < 4; g++) acc[mf][nf][g] = 0.0f;

    // GEMM1: K=256 (4 chunks of 64)
    gemm1(gw1, smc, smbase, mw, nw, lane, tid, acc);
    __syncthreads();   // all chunk-3 reads (sA + WB) done

    // prefetch ALL of w2 (32KB) while we do epilogue math
    issueW2(gw2, smbase, tid);
    cp_commit();

    // epilogue 1: h = silu(acc + b1 [+ dist*w1_last]) -> fp16 -> A cols 0..127
#pragma unroll
    for (int mf = 0; mf < 2; mf++) {
        int r0 = mw * 32 + mf * 16 + (lane >> 2);
        int r1 = r0 + 8;
        float d0 = EDGE ? sDst[r0] : 0.0f;
        float d1 = EDGE ? sDst[r1] : 0.0f;
#pragma unroll
        for (int nf = 0; nf < 8; nf++) {
            int c0 = nw * 64 + nf * 8 + (lane & 3) * 2;
            float* v = acc[mf][nf];
            float wl0 = EDGE ? sW1l[c0] : 0.0f;
            float wl1 = EDGE ? sW1l[c0 + 1] : 0.0f;
            float h00 = silu_f(v[0] + sB1[c0]     + d0 * wl0);
            float h01 = silu_f(v[1] + sB1[c0 + 1] + d0 * wl1);
            float h10 = silu_f(v[2] + sB1[c0]     + d1 * wl0);
            float h11 = silu_f(v[3] + sB1[c0 + 1] + d1 * wl1);
            *(half2*)(smc + r0 * APB + c0 * 2) = __floats2half2_rn(h00, h01);
            *(half2*)(smc + r1 * APB + c0 * 2) = __floats2half2_rn(h10, h11);
            v[0] = v[1] = v[2] = v[3] = 0.0f;
        }
    }
    cp_wait<0>();
    __syncthreads();   // w2 + h tiles visible to all

    // GEMM2: K=128, un-barriered
    gemm2(smc, smbase, mw, nw, lane, acc);
    __syncthreads();   // all A reads done before fp32 overlay

    // epilogue 2: stage fp32 result over the A tile region (h is dead now)
#pragma unroll
    for (int mf = 0; mf < 2; mf++) {
        int r0 = mw * 32 + mf * 16 + (lane >> 2);
        int r1 = r0 + 8;
#pragma unroll
        for (int nf = 0; nf < 8; nf++) {
            int c0 = nw * 64 + nf * 8 + (lane & 3) * 2;
            float* v = acc[mf][nf];
            float o00 = v[0] + sB2[c0];
            float o01 = v[1] + sB2[c0 + 1];
            float o10 = v[2] + sB2[c0];
            float o11 = v[3] + sB2[c0 + 1];
            if (EDGE) {
                o00 = silu_f(o00); o01 = silu_f(o01);
                o10 = silu_f(o10); o11 = silu_f(o11);
            }
            *(float2*)(smc + r0 * APB + c0 * 4) = make_float2(o00, o01);
            *(float2*)(smc + r1 * APB + c0 * 4) = make_float2(o10, o11);
        }
    }
    __syncthreads();

    // writeout: 128 rows x 2 halves, scatter-add or store
    {
        int r = tid >> 1, half = tid & 1;
        const float4* src = (const float4*)(smc + r * APB + half * 256);
        if (EDGE) {
            int rc = sRec[r];
            if (rc >= 0) {
                float* dst = &g_aggr[(size_t)rc * HDIM + half * 64];
#pragma unroll
                for (int j = 0; j < 16; j++) {
                    float4 v = src[j];
                    red4(dst + j * 4, v.x, v.y, v.z, v.w);
                }
            }
        } else {
            int gn = m0 + r;
            if (gn < M) {
                float4* dst = (float4*)&out[(size_t)gn * HDIM + half * 64];
#pragma unroll
                for (int j = 0; j < 16; j++) dst[j] = src[j];
            }
        }
    }
}

// ------------------------- launch -------------------------
extern "C" void kernel_launch(void* const* d_in, const int* in_sizes, int n_in,
                              void* d_out, int out_size) {
    const float* x   = (const float*)d_in[0];
    const float* pos = (const float*)d_in[1];
    const int*   ei  = (const int*)d_in[2];
    const float* mw1 = (const float*)d_in[3];
    const float* mb1 = (const float*)d_in[4];
    const float* mw2 = (const float*)d_in[5];
    const float* mb2 = (const float*)d_in[6];
    const float* uw1 = (const float*)d_in[7];
    const float* ub1 = (const float*)d_in[8];
    const float* uw2 = (const float*)d_in[9];
    const float* ub2 = (const float*)d_in[10];

    int N = in_sizes[0] / HDIM;
    int E = in_sizes[2] / 2;

    cudaFuncSetAttribute(mlp_mma_kernel<true>,
                         cudaFuncAttributeMaxDynamicSharedMemorySize, SMEM_BYTES);
    cudaFuncSetAttribute(mlp_mma_kernel<false>,
                         cudaFuncAttributeMaxDynamicSharedMemorySize, SMEM_BYTES);

    prep_all<<<2048, 256>>>(ei, pos, x, mw1, mw2, uw1, uw2, N, E);
    mlp_mma_kernel<true><<<(E + TMR - 1) / TMR, 256, SMEM_BYTES>>>(
        mw1, mb1, mb2, nullptr, E);
    mlp_mma_kernel<false><<<(N + TMR - 1) / TMR, 256, SMEM_BYTES>>>(
        uw1, ub1, ub2, (float*)d_out, N);
}

// round 14
// speedup vs baseline: 1.2620x; 1.2620x over previous
#include <cuda_runtime.h>
#include <cuda_fp16.h>
#include <math.h>
#include <stdint.h>

#define HDIM 128
#define MAXN 50000
#define MAXE 640000
#define TMR  128                    // rows per CTA tile

// byte-offset shared layout
#define APB     528                 // A row pitch bytes (264 halves)
#define WB_B    (TMR * APB)         // 67584
#define WB_CHB  16384               // one 64k x 128n fp16 chunk, frag-ordered
#define B1_B    (WB_B + 2 * WB_CHB) // 100352
#define B2_B    (B1_B + 512)
#define W1L_B   (B2_B + 512)
#define DIST_B  (W1L_B + 512)
#define REC_B   (DIST_B + 512)
#define SEND_B  (REC_B + 512)
#define SMEM_BYTES (SEND_B + 512)   // 103424 -> 2 CTAs/SM

// ------------------------- device scratch -------------------------
__device__ __align__(16) float  g_aggr[(size_t)MAXN * HDIM];
__device__ __align__(16) __half g_x16[(size_t)MAXN * HDIM];
__device__ int   g_send[MAXE];
__device__ int   g_rec[MAXE];
__device__ float g_dist[MAXE];
// frag-ordered fp16 weights: [kchunk64][nb*4+ks][lane][reg] packed as halves
__device__ __align__(16) __half g_w1h[4 * 8192];   // edge w1, K=256
__device__ __align__(16) __half g_w2h[2 * 8192];   // edge w2, K=128
__device__ __align__(16) __half g_u1h[4 * 8192];   // node w1, K=256
__device__ __align__(16) __half g_u2h[2 * 8192];   // node w2, K=128

// ------------------------- helpers -------------------------
__device__ __forceinline__ float silu_f(float v) {
    return __fdividef(v, 1.0f + __expf(-v));
}
__device__ __forceinline__ uint32_t cvta_sh(const void* p) {
    uint32_t a;
    asm("{ .reg .u64 t; cvta.to.shared.u64 t, %1; cvt.u32.u64 %0, t; }"
        : "=r"(a) : "l"(p));
    return a;
}
__device__ __forceinline__ void mma16(float d[4], const uint32_t a[4],
                                      const uint32_t b[2]) {
    asm volatile(
        "mma.sync.aligned.m16n8k16.row.col.f32.f16.f16.f32 "
        "{%0,%1,%2,%3},{%4,%5,%6,%7},{%8,%9},{%0,%1,%2,%3};"
        : "+f"(d[0]), "+f"(d[1]), "+f"(d[2]), "+f"(d[3])
        : "r"(a[0]), "r"(a[1]), "r"(a[2]), "r"(a[3]), "r"(b[0]), "r"(b[1]));
}
__device__ __forceinline__ void ldsm4(uint32_t r[4], uint32_t addr) {
    asm volatile("ldmatrix.sync.aligned.m8n8.x4.shared.b16 {%0,%1,%2,%3}, [%4];"
                 : "=r"(r[0]), "=r"(r[1]), "=r"(r[2]), "=r"(r[3]) : "r"(addr));
}
__device__ __forceinline__ void red4(float* p, float a, float b, float c, float d) {
    asm volatile("red.global.add.v4.f32 [%0], {%1,%2,%3,%4};"
                 :: "l"(p), "f"(a), "f"(b), "f"(c), "f"(d) : "memory");
}
__device__ __forceinline__ void cp16(uint32_t dst_sh, const void* src) {
    asm volatile("cp.async.ca.shared.global [%0], [%1], 16;"
                 :: "r"(dst_sh), "l"(src) : "memory");
}
__device__ __forceinline__ void cp_commit() {
    asm volatile("cp.async.commit_group;" ::: "memory");
}
template <int W>
__device__ __forceinline__ void cp_wait() {
    asm volatile("cp.async.wait_group %0;" :: "n"(W) : "memory");
}

// frag-order half-index for weight element (n, k), 64k-chunks.
// word = chunkbase + (nb*4+ks)*64 + lane*2 + reg
__device__ __forceinline__ int fragh(int n, int k) {
    int kc   = k >> 6;
    int ks   = (k >> 4) & 3;
    int reg  = (k >> 3) & 1;
    int lane = (n & 7) * 4 + ((k >> 1) & 3);
    int idx32 = kc * 4096 + (((n >> 3) * 4 + ks) << 6) + lane * 2 + reg;
    return idx32 * 2 + (k & 1);
}

// ------------------------- fused prep kernel -------------------------
__global__ void prep_all(const int* __restrict__ ei32,
                         const float* __restrict__ pos,
                         const float* __restrict__ x,
                         const float* __restrict__ mw1, const float* __restrict__ mw2,
                         const float* __restrict__ uw1, const float* __restrict__ uw2,
                         int N, int E) {
    bool is64 = true;
#pragma unroll
    for (int t = 0; t < 16; t++) is64 &= (ei32[2 * t + 1] == 0);

    const long long NH = (long long)N * HDIM;
    const long long t0 = NH;                 // zero aggr
    const long long t1 = t0 + NH;            // x -> fp16
    const long long t2 = t1 + E;             // edges
    const long long t3 = t2 + 32768;         // edge w1
    const long long t4 = t3 + 16384;         // edge w2
    const long long t5 = t4 + 32768;         // node w1
    const long long t6 = t5 + 16384;         // node w2

    long long i = (long long)blockIdx.x * blockDim.x + threadIdx.x;
    long long st = (long long)gridDim.x * blockDim.x;
    for (; i < t6; i += st) {
        if (i < t0) {
            g_aggr[i] = 0.0f;
        } else if (i < t1) {
            long long j = i - t0;
            g_x16[j] = __float2half_rn(x[j]);
        } else if (i < t2) {
            int e = (int)(i - t1);
            int s, r;
            if (is64) { s = ei32[2 * (size_t)e]; r = ei32[2 * ((size_t)E + e)]; }
            else      { s = ei32[e];             r = ei32[(size_t)E + e]; }
            s = min(max(s, 0), N - 1);
            r = min(max(r, 0), N - 1);
            g_send[e] = s;
            g_rec[e]  = r;
            float dx = pos[s * 3 + 0] - pos[r * 3 + 0];
            float dy = pos[s * 3 + 1] - pos[r * 3 + 1];
            float dz = pos[s * 3 + 2] - pos[r * 3 + 2];
            g_dist[e] = sqrtf(dx * dx + dy * dy + dz * dz);
        } else if (i < t3) {
            int j = (int)(i - t2);
            int n = j >> 8, k = j & 255;
            g_w1h[fragh(n, k)] = __float2half_rn(mw1[k * 128 + n]);
        } else if (i < t4) {
            int j = (int)(i - t3);
            int n = j >> 7, k = j & 127;
            g_w2h[fragh(n, k)] = __float2half_rn(mw2[k * 128 + n]);
        } else if (i < t5) {
            int j = (int)(i - t4);
            int n = j >> 8, k = j & 255;
            g_u1h[fragh(n, k)] = __float2half_rn(uw1[k * 128 + n]);
        } else {
            int j = (int)(i - t5);
            int n = j >> 7, k = j & 127;
            g_u2h[fragh(n, k)] = __float2half_rn(uw2[k * 128 + n]);
        }
    }
}

// ------------------------- fp16 mma GEMMs (32x64 warp tiles, 8 warps) --------
__device__ __forceinline__ void issueB1(const __half* __restrict__ gB, int c,
                                        int buf, uint32_t smbase, int tid) {
#pragma unroll
    for (int it = 0; it < 4; it++) {
        int idx = (tid + it * 256) * 16;
        cp16(smbase + WB_B + buf * WB_CHB + idx, (const char*)gB + c * WB_CHB + idx);
    }
}
__device__ __forceinline__ void issueW2(const __half* __restrict__ gB,
                                        uint32_t smbase, int tid) {
#pragma unroll
    for (int it = 0; it < 8; it++) {
        int idx = (tid + it * 256) * 16;
        cp16(smbase + WB_B + idx, (const char*)gB + idx);
    }
}

// per-thread ldmatrix A base row address (mf=0), koff folded in
__device__ __forceinline__ uint32_t a_addr(uint32_t smbase, int mw, int lane) {
    int row  = mw * 32 + (lane & 7) + ((lane >> 3) & 1) * 8;
    int koff = (lane >> 4) * 8;           // halves
    return smbase + row * APB + koff * 2;
}

// Single barrier per chunk; chunk 0 already in flight (committed by caller).
// Caller must __syncthreads() after return before mutating sA or WB.
__device__ __forceinline__ void gemm1(const __half* __restrict__ gB,
                                      char* smc, uint32_t smbase,
                                      int mw, int nw, int lane, int tid,
                                      float acc[2][8][4]) {
    const uint32_t abase = a_addr(smbase, mw, lane);
    for (int c = 0; c < 4; c++) {
        cp_wait<0>();
        __syncthreads();   // chunk c visible; chunk c-1 reads all done
        if (c + 1 < 4) {
            issueB1(gB, c + 1, (c + 1) & 1, smbase, tid);
            cp_commit();
        }
        const char* wb = smc + WB_B + (c & 1) * WB_CHB;
#pragma unroll
        for (int ks = 0; ks < 4; ks++) {
            uint32_t a[2][4];
            uint2    b[8];
#pragma unroll
            for (int mf = 0; mf < 2; mf++)
                ldsm4(a[mf], abase + mf * 16 * APB + (c * 64 + ks * 16) * 2);
#pragma unroll
            for (int nf = 0; nf < 8; nf++) {
                int nb = nw * 8 + nf;
                b[nf] = *(const uint2*)(wb + (((nb * 4 + ks) << 5) + lane) * 8);
            }
#pragma unroll
            for (int mf = 0; mf < 2; mf++)
#pragma unroll
                for (int nf = 0; nf < 8; nf++)
                    mma16(acc[mf][nf], a[mf], (const uint32_t*)&b[nf]);
        }
    }
}

// GEMM2: whole K=128 in one 32KB frag buffer, no internal barriers
__device__ __forceinline__ void gemm2(char* smc, uint32_t smbase,
                                      int mw, int nw, int lane,
                                      float acc[2][8][4]) {
    const uint32_t abase = a_addr(smbase, mw, lane);
#pragma unroll
    for (int ks8 = 0; ks8 < 8; ks8++) {
        const char* wb = smc + WB_B + (ks8 >> 2) * WB_CHB;
        int ks = ks8 & 3;
        uint32_t a[2][4];
        uint2    b[8];
#pragma unroll
        for (int mf = 0; mf < 2; mf++)
            ldsm4(a[mf], abase + mf * 16 * APB + (ks8 * 16) * 2);
#pragma unroll
        for (int nf = 0; nf < 8; nf++) {
            int nb = nw * 8 + nf;
            b[nf] = *(const uint2*)(wb + (((nb * 4 + ks) << 5) + lane) * 8);
        }
#pragma unroll
        for (int mf = 0; mf < 2; mf++)
#pragma unroll
            for (int nf = 0; nf < 8; nf++)
                mma16(acc[mf][nf], a[mf], (const uint32_t*)&b[nf]);
    }
}

// ------------------------- fused MLP kernel (edge / node) -------------------------
template <bool EDGE>
__global__ void __launch_bounds__(256, 2) mlp_mma_kernel(
    const float* __restrict__ w1full,   // original w1 (dist row, edge only)
    const float* __restrict__ b1, const float* __restrict__ b2,
    float* __restrict__ out, int M) {
    extern __shared__ char smc[];
    const uint32_t smbase = cvta_sh(smc);
    float* sB1  = (float*)(smc + B1_B);
    float* sB2  = (float*)(smc + B2_B);
    float* sW1l = (float*)(smc + W1L_B);
    float* sDst = (float*)(smc + DIST_B);
    int*   sRec = (int*)(smc + REC_B);
    int*   sSnd = (int*)(smc + SEND_B);

    const __half* gw1 = EDGE ? g_w1h : g_u1h;
    const __half* gw2 = EDGE ? g_w2h : g_u2h;

    const int tid  = threadIdx.x;
    const int lane = tid & 31;
    const int wid  = tid >> 5;
    const int mw   = wid >> 1;   // 0..3 (32-row block)
    const int nw   = wid & 1;    // 0..1 (64-col block)
    const int m0   = blockIdx.x * TMR;

    // w1 chunk 0 into flight immediately — overlaps bias loads + gather
    issueB1(gw1, 0, 0, smbase, tid);
    cp_commit();

    if (tid < 128) {
        sB1[tid] = b1[tid];
        sB2[tid] = b2[tid];
        if (EDGE) {
            sW1l[tid] = w1full[(size_t)256 * 128 + tid];
            int ge = m0 + tid;
            if (ge < M) {
                sSnd[tid] = g_send[ge];
                sRec[tid] = g_rec[ge];
                sDst[tid] = g_dist[ge];
            } else {
                sSnd[tid] = 0; sRec[tid] = -1; sDst[tid] = 0.0f;
            }
        }
    }
    __syncthreads();

    // gather state rows (LDG.128 -> STS.128): cols 0..127 from x16; 128..255
    // from x16 (edge) or aggr fp32->fp16 (node)
    const uint4* x16 = (const uint4*)g_x16;   // 16 uint4 per row
    for (int i = tid; i < TMR * 16; i += 256) {
        int r = i >> 4, c = i & 15;
        if (EDGE) {
            int s  = sSnd[r];
            int rc = sRec[r];
            if (rc < 0) rc = 0;
            uint4 vs = x16[(size_t)s * 16 + c];
            uint4 vr = x16[(size_t)rc * 16 + c];
            *(uint4*)(smc + r * APB + c * 16)       = vs;
            *(uint4*)(smc + r * APB + 256 + c * 16) = vr;
        } else {
            int gn = m0 + r;
            if (gn >= M) gn = M - 1;
            uint4 vx = x16[(size_t)gn * 16 + c];
            *(uint4*)(smc + r * APB + c * 16) = vx;
            const float4* ar = (const float4*)&g_aggr[(size_t)gn * HDIM + c * 8];
            float4 a0 = ar[0], a1 = ar[1];
            uint4 u;
            ((half2*)&u)[0] = __floats2half2_rn(a0.x, a0.y);
            ((half2*)&u)[1] = __floats2half2_rn(a0.z, a0.w);
            ((half2*)&u)[2] = __floats2half2_rn(a1.x, a1.y);
            ((half2*)&u)[3] = __floats2half2_rn(a1.z, a1.w);
            *(uint4*)(smc + r * APB + 256 + c * 16) = u;
        }
    }
    // (first gemm chunk's bar orders the gather)

    float acc[2][8][4];
#pragma unroll
    for (int mf = 0; mf < 2; mf++)
#pragma unroll
        for (int nf = 0; nf < 8; nf++)
#pragma unroll
            for (int g = 0; g < 4; g++) acc[mf][nf][g] = 0.0f;

    // GEMM1: K=256 (4 chunks of 64)
    gemm1(gw1, smc, smbase, mw, nw, lane, tid, acc);
    __syncthreads();   // all chunk-3 reads (sA + WB) done

    // prefetch ALL of w2 (32KB) while we do epilogue math
    issueW2(gw2, smbase, tid);
    cp_commit();

    // epilogue 1: h = silu(acc + b1 [+ dist*w1_last]) -> fp16 -> A cols 0..127
#pragma unroll
    for (int mf = 0; mf < 2; mf++) {
        int r0 = mw * 32 + mf * 16 + (lane >> 2);
        int r1 = r0 + 8;
        float d0 = EDGE ? sDst[r0] : 0.0f;
        float d1 = EDGE ? sDst[r1] : 0.0f;
#pragma unroll
        for (int nf = 0; nf < 8; nf++) {
            int c0 = nw * 64 + nf * 8 + (lane & 3) * 2;
            float* v = acc[mf][nf];
            float wl0 = EDGE ? sW1l[c0] : 0.0f;
            float wl1 = EDGE ? sW1l[c0 + 1] : 0.0f;
            float h00 = silu_f(v[0] + sB1[c0]     + d0 * wl0);
            float h01 = silu_f(v[1] + sB1[c0 + 1] + d0 * wl1);
            float h10 = silu_f(v[2] + sB1[c0]     + d1 * wl0);
            float h11 = silu_f(v[3] + sB1[c0 + 1] + d1 * wl1);
            *(half2*)(smc + r0 * APB + c0 * 2) = __floats2half2_rn(h00, h01);
            *(half2*)(smc + r1 * APB + c0 * 2) = __floats2half2_rn(h10, h11);
            v[0] = v[1] = v[2] = v[3] = 0.0f;
        }
    }
    cp_wait<0>();
    __syncthreads();   // w2 + h tiles visible to all

    // GEMM2: K=128, un-barriered
    gemm2(smc, smbase, mw, nw, lane, acc);
    __syncthreads();   // all A reads done before fp32 overlay

    // epilogue 2: stage fp32 result over the A tile region (h is dead now)
#pragma unroll
    for (int mf = 0; mf < 2; mf++) {
        int r0 = mw * 32 + mf * 16 + (lane >> 2);
        int r1 = r0 + 8;
#pragma unroll
        for (int nf = 0; nf < 8; nf++) {
            int c0 = nw * 64 + nf * 8 + (lane & 3) * 2;
            float* v = acc[mf][nf];
            float o00 = v[0] + sB2[c0];
            float o01 = v[1] + sB2[c0 + 1];
            float o10 = v[2] + sB2[c0];
            float o11 = v[3] + sB2[c0 + 1];
            if (EDGE) {
                o00 = silu_f(o00); o01 = silu_f(o01);
                o10 = silu_f(o10); o11 = silu_f(o11);
            }
            *(float2*)(smc + r0 * APB + c0 * 4) = make_float2(o00, o01);
            *(float2*)(smc + r1 * APB + c0 * 4) = make_float2(o10, o11);
        }
    }
    __syncthreads();

    // writeout: 128 rows x 2 halves, scatter-add or store
    {
        int r = tid >> 1, half = tid & 1;
        const float4* src = (const float4*)(smc + r * APB + half * 256);
        if (EDGE) {
            int rc = sRec[r];
            if (rc >= 0) {
                float* dst = &g_aggr[(size_t)rc * HDIM + half * 64];
#pragma unroll
                for (int j = 0; j < 16; j++) {
                    float4 v = src[j];
                    red4(dst + j * 4, v.x, v.y, v.z, v.w);
                }
            }
        } else {
            int gn = m0 + r;
            if (gn < M) {
                float4* dst = (float4*)&out[(size_t)gn * HDIM + half * 64];
#pragma unroll
                for (int j = 0; j < 16; j++) dst[j] = src[j];
            }
        }
    }
}

// ------------------------- launch -------------------------
extern "C" void kernel_launch(void* const* d_in, const int* in_sizes, int n_in,
                              void* d_out, int out_size) {
    const float* x   = (const float*)d_in[0];
    const float* pos = (const float*)d_in[1];
    const int*   ei  = (const int*)d_in[2];
    const float* mw1 = (const float*)d_in[3];
    const float* mb1 = (const float*)d_in[4];
    const float* mw2 = (const float*)d_in[5];
    const float* mb2 = (const float*)d_in[6];
    const float* uw1 = (const float*)d_in[7];
    const float* ub1 = (const float*)d_in[8];
    const float* uw2 = (const float*)d_in[9];
    const float* ub2 = (const float*)d_in[10];

    int N = in_sizes[0] / HDIM;
    int E = in_sizes[2] / 2;

    cudaFuncSetAttribute(mlp_mma_kernel<true>,
                         cudaFuncAttributeMaxDynamicSharedMemorySize, SMEM_BYTES);
    cudaFuncSetAttribute(mlp_mma_kernel<false>,
                         cudaFuncAttributeMaxDynamicSharedMemorySize, SMEM_BYTES);

    prep_all<<<2048, 256>>>(ei, pos, x, mw1, mw2, uw1, uw2, N, E);
    mlp_mma_kernel<true><<<(E + TMR - 1) / TMR, 256, SMEM_BYTES>>>(
        mw1, mb1, mb2, nullptr, E);
    mlp_mma_kernel<false><<<(N + TMR - 1) / TMR, 256, SMEM_BYTES>>>(
        uw1, ub1, ub2, (float*)d_out, N);
}

// round 15
// speedup vs baseline: 1.3137x; 1.0410x over previous
#include <cuda_runtime.h>
#include <cuda_fp16.h>
#include <math.h>
#include <stdint.h>

#define HDIM 128
#define MAXN 50000
#define MAXE 640000
#define TMR  128                    // rows per CTA tile

// byte-offset shared layout
#define APB     528                 // A row pitch bytes (264 halves)
#define WB_B    (TMR * APB)         // 67584
#define WB_CHB  16384               // one 64k x 128n fp16 chunk, frag-ordered
#define B1_B    (WB_B + 2 * WB_CHB) // 100352
#define B2_B    (B1_B + 512)
#define W1L_B   (B2_B + 512)
#define DIST_B  (W1L_B + 512)
#define REC_B   (DIST_B + 512)
#define SEND_B  (REC_B + 512)
#define SMEM_BYTES (SEND_B + 512)   // 103424 -> 2 CTAs/SM

// ------------------------- device scratch -------------------------
__device__ __align__(16) float  g_aggr[(size_t)MAXN * HDIM];
__device__ __align__(16) __half g_x16[(size_t)MAXN * HDIM];
__device__ int   g_send[MAXE];
__device__ int   g_rec[MAXE];
__device__ float g_dist[MAXE];
// frag-ordered fp16 weights: [kchunk64][nb*4+ks][lane][reg] packed as halves
__device__ __align__(16) __half g_w1h[4 * 8192];   // edge w1, K=256
__device__ __align__(16) __half g_w2h[2 * 8192];   // edge w2, K=128
__device__ __align__(16) __half g_u1h[4 * 8192];   // node w1, K=256
__device__ __align__(16) __half g_u2h[2 * 8192];   // node w2, K=128

// ------------------------- helpers -------------------------
// silu(v) = v * sigmoid(v) = 0.5*v*(1 + tanh(v/2)); tanh.approx = 1 MUFU
__device__ __forceinline__ float silu_f(float v) {
    float t;
    asm("tanh.approx.f32 %0, %1;" : "=f"(t) : "f"(0.5f * v));
    return 0.5f * v * (1.0f + t);
}
__device__ __forceinline__ uint32_t cvta_sh(const void* p) {
    uint32_t a;
    asm("{ .reg .u64 t; cvta.to.shared.u64 t, %1; cvt.u32.u64 %0, t; }"
        : "=r"(a) : "l"(p));
    return a;
}
__device__ __forceinline__ void mma16(float d[4], const uint32_t a[4],
                                      const uint32_t b[2]) {
    asm volatile(
        "mma.sync.aligned.m16n8k16.row.col.f32.f16.f16.f32 "
        "{%0,%1,%2,%3},{%4,%5,%6,%7},{%8,%9},{%0,%1,%2,%3};"
        : "+f"(d[0]), "+f"(d[1]), "+f"(d[2]), "+f"(d[3])
        : "r"(a[0]), "r"(a[1]), "r"(a[2]), "r"(a[3]), "r"(b[0]), "r"(b[1]));
}
__device__ __forceinline__ void ldsm4(uint32_t r[4], uint32_t addr) {
    asm volatile("ldmatrix.sync.aligned.m8n8.x4.shared.b16 {%0,%1,%2,%3}, [%4];"
                 : "=r"(r[0]), "=r"(r[1]), "=r"(r[2]), "=r"(r[3]) : "r"(addr));
}
__device__ __forceinline__ void red4(float* p, float a, float b, float c, float d) {
    asm volatile("red.global.add.v4.f32 [%0], {%1,%2,%3,%4};"
                 :: "l"(p), "f"(a), "f"(b), "f"(c), "f"(d) : "memory");
}
__device__ __forceinline__ void cp16(uint32_t dst_sh, const void* src) {
    asm volatile("cp.async.ca.shared.global [%0], [%1], 16;"
                 :: "r"(dst_sh), "l"(src) : "memory");
}
__device__ __forceinline__ void cp_commit() {
    asm volatile("cp.async.commit_group;" ::: "memory");
}
template <int W>
__device__ __forceinline__ void cp_wait() {
    asm volatile("cp.async.wait_group %0;" :: "n"(W) : "memory");
}

// frag-order half-index for weight element (n, k), 64k-chunks.
// word = chunkbase + (nb*4+ks)*64 + lane*2 + reg
__device__ __forceinline__ int fragh(int n, int k) {
    int kc   = k >> 6;
    int ks   = (k >> 4) & 3;
    int reg  = (k >> 3) & 1;
    int lane = (n & 7) * 4 + ((k >> 1) & 3);
    int idx32 = kc * 4096 + (((n >> 3) * 4 + ks) << 6) + lane * 2 + reg;
    return idx32 * 2 + (k & 1);
}

// ------------------------- fused prep kernel (aggr zeroed by memset) ---------
__global__ void prep_all(const int* __restrict__ ei32,
                         const float* __restrict__ pos,
                         const float* __restrict__ x,
                         const float* __restrict__ mw1, const float* __restrict__ mw2,
                         const float* __restrict__ uw1, const float* __restrict__ uw2,
                         int N, int E) {
    bool is64 = true;
#pragma unroll
    for (int t = 0; t < 16; t++) is64 &= (ei32[2 * t + 1] == 0);

    const long long NH = (long long)N * HDIM;
    const long long t1 = NH;                 // x -> fp16
    const long long t2 = t1 + E;             // edges
    const long long t3 = t2 + 32768;         // edge w1
    const long long t4 = t3 + 16384;         // edge w2
    const long long t5 = t4 + 32768;         // node w1
    const long long t6 = t5 + 16384;         // node w2

    long long i = (long long)blockIdx.x * blockDim.x + threadIdx.x;
    long long st = (long long)gridDim.x * blockDim.x;
    for (; i < t6; i += st) {
        if (i < t1) {
            g_x16[i] = __float2half_rn(x[i]);
        } else if (i < t2) {
            int e = (int)(i - t1);
            int s, r;
            if (is64) { s = ei32[2 * (size_t)e]; r = ei32[2 * ((size_t)E + e)]; }
            else      { s = ei32[e];             r = ei32[(size_t)E + e]; }
            s = min(max(s, 0), N - 1);
            r = min(max(r, 0), N - 1);
            g_send[e] = s;
            g_rec[e]  = r;
            float dx = pos[s * 3 + 0] - pos[r * 3 + 0];
            float dy = pos[s * 3 + 1] - pos[r * 3 + 1];
            float dz = pos[s * 3 + 2] - pos[r * 3 + 2];
            g_dist[e] = sqrtf(dx * dx + dy * dy + dz * dz);
        } else if (i < t3) {
            int j = (int)(i - t2);
            int n = j >> 8, k = j & 255;
            g_w1h[fragh(n, k)] = __float2half_rn(mw1[k * 128 + n]);
        } else if (i < t4) {
            int j = (int)(i - t3);
            int n = j >> 7, k = j & 127;
            g_w2h[fragh(n, k)] = __float2half_rn(mw2[k * 128 + n]);
        } else if (i < t5) {
            int j = (int)(i - t4);
            int n = j >> 8, k = j & 255;
            g_u1h[fragh(n, k)] = __float2half_rn(uw1[k * 128 + n]);
        } else {
            int j = (int)(i - t5);
            int n = j >> 7, k = j & 127;
            g_u2h[fragh(n, k)] = __float2half_rn(uw2[k * 128 + n]);
        }
    }
}

// ------------------------- fp16 mma GEMMs (32x64 warp tiles, 8 warps) --------
__device__ __forceinline__ void issueB1(const __half* __restrict__ gB, int c,
                                        int buf, uint32_t smbase, int tid) {
#pragma unroll
    for (int it = 0; it < 4; it++) {
        int idx = (tid + it * 256) * 16;
        cp16(smbase + WB_B + buf * WB_CHB + idx, (const char*)gB + c * WB_CHB + idx);
    }
}
__device__ __forceinline__ void issueW2(const __half* __restrict__ gB,
                                        uint32_t smbase, int tid) {
#pragma unroll
    for (int it = 0; it < 8; it++) {
        int idx = (tid + it * 256) * 16;
        cp16(smbase + WB_B + idx, (const char*)gB + idx);
    }
}

// per-thread ldmatrix A base row address (mf=0), koff folded in
__device__ __forceinline__ uint32_t a_addr(uint32_t smbase, int mw, int lane) {
    int row  = mw * 32 + (lane & 7) + ((lane >> 3) & 1) * 8;
    int koff = (lane >> 4) * 8;           // halves
    return smbase + row * APB + koff * 2;
}

// Single barrier per chunk; chunk 0 already in flight (committed by caller).
// Caller must __syncthreads() after return before mutating sA or WB.
__device__ __forceinline__ void gemm1(const __half* __restrict__ gB,
                                      char* smc, uint32_t smbase,
                                      int mw, int nw, int lane, int tid,
                                      float acc[2][8][4]) {
    const uint32_t abase = a_addr(smbase, mw, lane);
    for (int c = 0; c < 4; c++) {
        cp_wait<0>();
        __syncthreads();   // chunk c visible; chunk c-1 reads all done
        if (c + 1 < 4) {
            issueB1(gB, c + 1, (c + 1) & 1, smbase, tid);
            cp_commit();
        }
        const char* wb = smc + WB_B + (c & 1) * WB_CHB;
#pragma unroll
        for (int ks = 0; ks < 4; ks++) {
            uint32_t a[2][4];
            uint2    b[8];
#pragma unroll
            for (int mf = 0; mf < 2; mf++)
                ldsm4(a[mf], abase + mf * 16 * APB + (c * 64 + ks * 16) * 2);
#pragma unroll
            for (int nf = 0; nf < 8; nf++) {
                int nb = nw * 8 + nf;
                b[nf] = *(const uint2*)(wb + (((nb * 4 + ks) << 5) + lane) * 8);
            }
#pragma unroll
            for (int mf = 0; mf < 2; mf++)
#pragma unroll
                for (int nf = 0; nf < 8; nf++)
                    mma16(acc[mf][nf], a[mf], (const uint32_t*)&b[nf]);
        }
    }
}

// GEMM2: whole K=128 in one 32KB frag buffer, no internal barriers
__device__ __forceinline__ void gemm2(char* smc, uint32_t smbase,
                                      int mw, int nw, int lane,
                                      float acc[2][8][4]) {
    const uint32_t abase = a_addr(smbase, mw, lane);
#pragma unroll
    for (int ks8 = 0; ks8 < 8; ks8++) {
        const char* wb = smc + WB_B + (ks8 >> 2) * WB_CHB;
        int ks = ks8 & 3;
        uint32_t a[2][4];
        uint2    b[8];
#pragma unroll
        for (int mf = 0; mf < 2; mf++)
            ldsm4(a[mf], abase + mf * 16 * APB + (ks8 * 16) * 2);
#pragma unroll
        for (int nf = 0; nf < 8; nf++) {
            int nb = nw * 8 + nf;
            b[nf] = *(const uint2*)(wb + (((nb * 4 + ks) << 5) + lane) * 8);
        }
#pragma unroll
        for (int mf = 0; mf < 2; mf++)
#pragma unroll
            for (int nf = 0; nf < 8; nf++)
                mma16(acc[mf][nf], a[mf], (const uint32_t*)&b[nf]);
    }
}

// ------------------------- fused MLP kernel (edge / node) -------------------------
template <bool EDGE>
__global__ void __launch_bounds__(256, 2) mlp_mma_kernel(
    const float* __restrict__ w1full,   // original w1 (dist row, edge only)
    const float* __restrict__ b1, const float* __restrict__ b2,
    float* __restrict__ out, int M) {
    extern __shared__ char smc[];
    const uint32_t smbase = cvta_sh(smc);
    float* sB1  = (float*)(smc + B1_B);
    float* sB2  = (float*)(smc + B2_B);
    float* sW1l = (float*)(smc + W1L_B);
    float* sDst = (float*)(smc + DIST_B);
    int*   sRec = (int*)(smc + REC_B);
    int*   sSnd = (int*)(smc + SEND_B);

    const __half* gw1 = EDGE ? g_w1h : g_u1h;
    const __half* gw2 = EDGE ? g_w2h : g_u2h;

    const int tid  = threadIdx.x;
    const int lane = tid & 31;
    const int wid  = tid >> 5;
    const int mw   = wid >> 1;   // 0..3 (32-row block)
    const int nw   = wid & 1;    // 0..1 (64-col block)
    const int m0   = blockIdx.x * TMR;

    // w1 chunk 0 into flight immediately — overlaps bias loads + gather
    issueB1(gw1, 0, 0, smbase, tid);
    cp_commit();

    if (tid < 128) {
        sB1[tid] = b1[tid];
        sB2[tid] = b2[tid];
        if (EDGE) {
            sW1l[tid] = w1full[(size_t)256 * 128 + tid];
            int ge = m0 + tid;
            if (ge < M) {
                sSnd[tid] = g_send[ge];
                sRec[tid] = g_rec[ge];
                sDst[tid] = g_dist[ge];
            } else {
                sSnd[tid] = 0; sRec[tid] = -1; sDst[tid] = 0.0f;
            }
        }
    }
    __syncthreads();

    // gather state rows (LDG.128 -> STS.128): cols 0..127 from x16; 128..255
    // from x16 (edge) or aggr fp32->fp16 (node)
    const uint4* x16 = (const uint4*)g_x16;   // 16 uint4 per row
    for (int i = tid; i < TMR * 16; i += 256) {
        int r = i >> 4, c = i & 15;
        if (EDGE) {
            int s  = sSnd[r];
            int rc = sRec[r];
            if (rc < 0) rc = 0;
            uint4 vs = x16[(size_t)s * 16 + c];
            uint4 vr = x16[(size_t)rc * 16 + c];
            *(uint4*)(smc + r * APB + c * 16)       = vs;
            *(uint4*)(smc + r * APB + 256 + c * 16) = vr;
        } else {
            int gn = m0 + r;
            if (gn >= M) gn = M - 1;
            uint4 vx = x16[(size_t)gn * 16 + c];
            *(uint4*)(smc + r * APB + c * 16) = vx;
            const float4* ar = (const float4*)&g_aggr[(size_t)gn * HDIM + c * 8];
            float4 a0 = ar[0], a1 = ar[1];
            uint4 u;
            ((half2*)&u)[0] = __floats2half2_rn(a0.x, a0.y);
            ((half2*)&u)[1] = __floats2half2_rn(a0.z, a0.w);
            ((half2*)&u)[2] = __floats2half2_rn(a1.x, a1.y);
            ((half2*)&u)[3] = __floats2half2_rn(a1.z, a1.w);
            *(uint4*)(smc + r * APB + 256 + c * 16) = u;
        }
    }
    // (first gemm chunk's bar orders the gather)

    float acc[2][8][4];
#pragma unroll
    for (int mf = 0; mf < 2; mf++)
#pragma unroll
        for (int nf = 0; nf < 8; nf++)
#pragma unroll
            for (int g = 0; g < 4; g++) acc[mf][nf][g] = 0.0f;

    // GEMM1: K=256 (4 chunks of 64)
    gemm1(gw1, smc, smbase, mw, nw, lane, tid, acc);
    __syncthreads();   // all chunk-3 reads (sA + WB) done

    // prefetch ALL of w2 (32KB) while we do epilogue math
    issueW2(gw2, smbase, tid);
    cp_commit();

    // epilogue 1: h = silu(acc + b1 [+ dist*w1_last]) -> fp16 -> A cols 0..127
#pragma unroll
    for (int mf = 0; mf < 2; mf++) {
        int r0 = mw * 32 + mf * 16 + (lane >> 2);
        int r1 = r0 + 8;
        float d0 = EDGE ? sDst[r0] : 0.0f;
        float d1 = EDGE ? sDst[r1] : 0.0f;
#pragma unroll
        for (int nf = 0; nf < 8; nf++) {
            int c0 = nw * 64 + nf * 8 + (lane & 3) * 2;
            float* v = acc[mf][nf];
            float wl0 = EDGE ? sW1l[c0] : 0.0f;
            float wl1 = EDGE ? sW1l[c0 + 1] : 0.0f;
            float h00 = silu_f(v[0] + sB1[c0]     + d0 * wl0);
            float h01 = silu_f(v[1] + sB1[c0 + 1] + d0 * wl1);
            float h10 = silu_f(v[2] + sB1[c0]     + d1 * wl0);
            float h11 = silu_f(v[3] + sB1[c0 + 1] + d1 * wl1);
            *(half2*)(smc + r0 * APB + c0 * 2) = __floats2half2_rn(h00, h01);
            *(half2*)(smc + r1 * APB + c0 * 2) = __floats2half2_rn(h10, h11);
            v[0] = v[1] = v[2] = v[3] = 0.0f;
        }
    }
    cp_wait<0>();
    __syncthreads();   // w2 + h tiles visible to all

    // GEMM2: K=128, un-barriered
    gemm2(smc, smbase, mw, nw, lane, acc);
    __syncthreads();   // all A reads done before fp32 overlay

    // epilogue 2: stage fp32 result over the A tile region (h is dead now)
#pragma unroll
    for (int mf = 0; mf < 2; mf++) {
        int r0 = mw * 32 + mf * 16 + (lane >> 2);
        int r1 = r0 + 8;
#pragma unroll
        for (int nf = 0; nf < 8; nf++) {
            int c0 = nw * 64 + nf * 8 + (lane & 3) * 2;
            float* v = acc[mf][nf];
            float o00 = v[0] + sB2[c0];
            float o01 = v[1] + sB2[c0 + 1];
            float o10 = v[2] + sB2[c0];
            float o11 = v[3] + sB2[c0 + 1];
            if (EDGE) {
                o00 = silu_f(o00); o01 = silu_f(o01);
                o10 = silu_f(o10); o11 = silu_f(o11);
            }
            *(float2*)(smc + r0 * APB + c0 * 4) = make_float2(o00, o01);
            *(float2*)(smc + r1 * APB + c0 * 4) = make_float2(o10, o11);
        }
    }
    __syncthreads();

    // writeout: 128 rows x 2 halves, scatter-add or store
    {
        int r = tid >> 1, half = tid & 1;
        const float4* src = (const float4*)(smc + r * APB + half * 256);
        if (EDGE) {
            int rc = sRec[r];
            if (rc >= 0) {
                float* dst = &g_aggr[(size_t)rc * HDIM + half * 64];
#pragma unroll
                for (int j = 0; j < 16; j++) {
                    float4 v = src[j];
                    red4(dst + j * 4, v.x, v.y, v.z, v.w);
                }
            }
        } else {
            int gn = m0 + r;
            if (gn < M) {
                float4* dst = (float4*)&out[(size_t)gn * HDIM + half * 64];
#pragma unroll
                for (int j = 0; j < 16; j++) dst[j] = src[j];
            }
        }
    }
}

// ------------------------- launch -------------------------
extern "C" void kernel_launch(void* const* d_in, const int* in_sizes, int n_in,
                              void* d_out, int out_size) {
    const float* x   = (const float*)d_in[0];
    const float* pos = (const float*)d_in[1];
    const int*   ei  = (const int*)d_in[2];
    const float* mw1 = (const float*)d_in[3];
    const float* mb1 = (const float*)d_in[4];
    const float* mw2 = (const float*)d_in[5];
    const float* mb2 = (const float*)d_in[6];
    const float* uw1 = (const float*)d_in[7];
    const float* ub1 = (const float*)d_in[8];
    const float* uw2 = (const float*)d_in[9];
    const float* ub2 = (const float*)d_in[10];

    int N = in_sizes[0] / HDIM;
    int E = in_sizes[2] / 2;

    cudaFuncSetAttribute(mlp_mma_kernel<true>,
                         cudaFuncAttributeMaxDynamicSharedMemorySize, SMEM_BYTES);
    cudaFuncSetAttribute(mlp_mma_kernel<false>,
                         cudaFuncAttributeMaxDynamicSharedMemorySize, SMEM_BYTES);

    // zero aggr at HBM rate (async memset, graph-capturable, no alloc)
    void* aggr_ptr = nullptr;
    cudaGetSymbolAddress(&aggr_ptr, g_aggr);
    cudaMemsetAsync(aggr_ptr, 0, (size_t)N * HDIM * sizeof(float));

    prep_all<<<2048, 256>>>(ei, pos, x, mw1, mw2, uw1, uw2, N, E);
    mlp_mma_kernel<true><<<(E + TMR - 1) / TMR, 256, SMEM_BYTES>>>(
        mw1, mb1, mb2, nullptr, E);
    mlp_mma_kernel<false><<<(N + TMR - 1) / TMR, 256, SMEM_BYTES>>>(
        uw1, ub1, ub2, (float*)d_out, N);
}

// round 16
// speedup vs baseline: 1.3368x; 1.0175x over previous
#include <cuda_runtime.h>
#include <cuda_fp16.h>
#include <math.h>
#include <stdint.h>

#define HDIM 128
#define MAXN 50000
#define MAXE 640000
#define TMR  128                    // rows per CTA tile

// byte-offset shared layout
#define APB     528                 // A row pitch bytes (264 halves)
#define WB_B    (TMR * APB)         // 67584
#define WB_CHB  16384               // one 64k x 128n fp16 chunk, frag-ordered
#define B1_B    (WB_B + 2 * WB_CHB) // 100352
#define B2_B    (B1_B + 512)
#define W1L_B   (B2_B + 512)
#define DIST_B  (W1L_B + 512)
#define REC_B   (DIST_B + 512)
#define SEND_B  (REC_B + 512)
#define SMEM_BYTES (SEND_B + 512)   // 103424 -> 2 CTAs/SM

// ------------------------- device scratch -------------------------
__device__ __align__(16) float  g_aggr[(size_t)MAXN * HDIM];
__device__ __align__(16) __half g_x16[(size_t)MAXN * HDIM];
__device__ int   g_send[MAXE];
__device__ int   g_rec[MAXE];
__device__ float g_dist[MAXE];
// frag-ordered fp16 weights: [kchunk64][nb*4+ks][lane][reg] packed as halves
__device__ __align__(16) __half g_w1h[4 * 8192];   // edge w1, K=256
__device__ __align__(16) __half g_w2h[2 * 8192];   // edge w2, K=128
__device__ __align__(16) __half g_u1h[4 * 8192];   // node w1, K=256
__device__ __align__(16) __half g_u2h[2 * 8192];   // node w2, K=128

// ------------------------- helpers -------------------------
// silu(v) = v * sigmoid(v) = 0.5*v*(1 + tanh(v/2)); tanh.approx = 1 MUFU
__device__ __forceinline__ float silu_f(float v) {
    float t;
    asm("tanh.approx.f32 %0, %1;" : "=f"(t) : "f"(0.5f * v));
    return 0.5f * v * (1.0f + t);
}
__device__ __forceinline__ uint32_t cvta_sh(const void* p) {
    uint32_t a;
    asm("{ .reg .u64 t; cvta.to.shared.u64 t, %1; cvt.u32.u64 %0, t; }"
        : "=r"(a) : "l"(p));
    return a;
}
__device__ __forceinline__ void mma16(float d[4], const uint32_t a[4],
                                      const uint32_t b[2]) {
    asm volatile(
        "mma.sync.aligned.m16n8k16.row.col.f32.f16.f16.f32 "
        "{%0,%1,%2,%3},{%4,%5,%6,%7},{%8,%9},{%0,%1,%2,%3};"
        : "+f"(d[0]), "+f"(d[1]), "+f"(d[2]), "+f"(d[3])
        : "r"(a[0]), "r"(a[1]), "r"(a[2]), "r"(a[3]), "r"(b[0]), "r"(b[1]));
}
__device__ __forceinline__ void ldsm4(uint32_t r[4], uint32_t addr) {
    asm volatile("ldmatrix.sync.aligned.m8n8.x4.shared.b16 {%0,%1,%2,%3}, [%4];"
                 : "=r"(r[0]), "=r"(r[1]), "=r"(r[2]), "=r"(r[3]) : "r"(addr));
}
__device__ __forceinline__ void red4(float* p, float a, float b, float c, float d) {
    asm volatile("red.global.add.v4.f32 [%0], {%1,%2,%3,%4};"
                 :: "l"(p), "f"(a), "f"(b), "f"(c), "f"(d) : "memory");
}
__device__ __forceinline__ void cp16(uint32_t dst_sh, const void* src) {
    asm volatile("cp.async.ca.shared.global [%0], [%1], 16;"
                 :: "r"(dst_sh), "l"(src) : "memory");
}
__device__ __forceinline__ void cp_commit() {
    asm volatile("cp.async.commit_group;" ::: "memory");
}
template <int W>
__device__ __forceinline__ void cp_wait() {
    asm volatile("cp.async.wait_group %0;" :: "n"(W) : "memory");
}

// frag-order half-index for weight element (n, k), 64k-chunks.
// word = chunkbase + (nb*4+ks)*64 + lane*2 + reg
__device__ __forceinline__ int fragh(int n, int k) {
    int kc   = k >> 6;
    int ks   = (k >> 4) & 3;
    int reg  = (k >> 3) & 1;
    int lane = (n & 7) * 4 + ((k >> 1) & 3);
    int idx32 = kc * 4096 + (((n >> 3) * 4 + ks) << 6) + lane * 2 + reg;
    return idx32 * 2 + (k & 1);
}

// ------------------------- fused prep kernel (aggr zeroed by memset) ---------
__global__ void prep_all(const int* __restrict__ ei32,
                         const float* __restrict__ pos,
                         const float* __restrict__ x,
                         const float* __restrict__ mw1, const float* __restrict__ mw2,
                         const float* __restrict__ uw1, const float* __restrict__ uw2,
                         int N, int E) {
    bool is64 = true;
#pragma unroll
    for (int t = 0; t < 16; t++) is64 &= (ei32[2 * t + 1] == 0);

    const long long NH  = (long long)N * HDIM;
    const long long NX8 = NH >> 3;           // x -> fp16, 8 elements per item
    const long long t1 = NX8;
    const long long t2 = t1 + E;             // edges
    const long long t3 = t2 + 32768;         // edge w1
    const long long t4 = t3 + 16384;         // edge w2
    const long long t5 = t4 + 32768;         // node w1
    const long long t6 = t5 + 16384;         // node w2

    long long i = (long long)blockIdx.x * blockDim.x + threadIdx.x;
    long long st = (long long)gridDim.x * blockDim.x;
    for (; i < t6; i += st) {
        if (i < t1) {
            long long j = i << 3;
            float4 a0 = *(const float4*)(x + j);
            float4 a1 = *(const float4*)(x + j + 4);
            uint4 u;
            ((half2*)&u)[0] = __floats2half2_rn(a0.x, a0.y);
            ((half2*)&u)[1] = __floats2half2_rn(a0.z, a0.w);
            ((half2*)&u)[2] = __floats2half2_rn(a1.x, a1.y);
            ((half2*)&u)[3] = __floats2half2_rn(a1.z, a1.w);
            *(uint4*)(g_x16 + j) = u;
        } else if (i < t2) {
            int e = (int)(i - t1);
            int s, r;
            if (is64) { s = ei32[2 * (size_t)e]; r = ei32[2 * ((size_t)E + e)]; }
            else      { s = ei32[e];             r = ei32[(size_t)E + e]; }
            s = min(max(s, 0), N - 1);
            r = min(max(r, 0), N - 1);
            g_send[e] = s;
            g_rec[e]  = r;
            float dx = pos[s * 3 + 0] - pos[r * 3 + 0];
            float dy = pos[s * 3 + 1] - pos[r * 3 + 1];
            float dz = pos[s * 3 + 2] - pos[r * 3 + 2];
            g_dist[e] = sqrtf(dx * dx + dy * dy + dz * dz);
        } else if (i < t3) {
            int j = (int)(i - t2);
            int n = j >> 8, k = j & 255;
            g_w1h[fragh(n, k)] = __float2half_rn(mw1[k * 128 + n]);
        } else if (i < t4) {
            int j = (int)(i - t3);
            int n = j >> 7, k = j & 127;
            g_w2h[fragh(n, k)] = __float2half_rn(mw2[k * 128 + n]);
        } else if (i < t5) {
            int j = (int)(i - t4);
            int n = j >> 8, k = j & 255;
            g_u1h[fragh(n, k)] = __float2half_rn(uw1[k * 128 + n]);
        } else {
            int j = (int)(i - t5);
            int n = j >> 7, k = j & 127;
            g_u2h[fragh(n, k)] = __float2half_rn(uw2[k * 128 + n]);
        }
    }
}

// ------------------------- fp16 mma GEMMs (32x64 warp tiles, 8 warps) --------
__device__ __forceinline__ void issueB1(const __half* __restrict__ gB, int c,
                                        int buf, uint32_t smbase, int tid) {
#pragma unroll
    for (int it = 0; it < 4; it++) {
        int idx = (tid + it * 256) * 16;
        cp16(smbase + WB_B + buf * WB_CHB + idx, (const char*)gB + c * WB_CHB + idx);
    }
}
__device__ __forceinline__ void issueW2(const __half* __restrict__ gB,
                                        uint32_t smbase, int tid) {
#pragma unroll
    for (int it = 0; it < 8; it++) {
        int idx = (tid + it * 256) * 16;
        cp16(smbase + WB_B + idx, (const char*)gB + idx);
    }
}

// per-thread ldmatrix A base row address (mf=0), koff folded in
__device__ __forceinline__ uint32_t a_addr(uint32_t smbase, int mw, int lane) {
    int row  = mw * 32 + (lane & 7) + ((lane >> 3) & 1) * 8;
    int koff = (lane >> 4) * 8;           // halves
    return smbase + row * APB + koff * 2;
}

// Single barrier per chunk; chunk 0 already in flight (committed by caller).
// Caller must __syncthreads() after return before mutating sA or WB.
__device__ __forceinline__ void gemm1(const __half* __restrict__ gB,
                                      char* smc, uint32_t smbase,
                                      int mw, int nw, int lane, int tid,
                                      float acc[2][8][4]) {
    const uint32_t abase = a_addr(smbase, mw, lane);
    for (int c = 0; c < 4; c++) {
        cp_wait<0>();
        __syncthreads();   // chunk c visible; chunk c-1 reads all done
        if (c + 1 < 4) {
            issueB1(gB, c + 1, (c + 1) & 1, smbase, tid);
            cp_commit();
        }
        const char* wb = smc + WB_B + (c & 1) * WB_CHB;
#pragma unroll
        for (int ks = 0; ks < 4; ks++) {
            uint32_t a[2][4];
            uint2    b[8];
#pragma unroll
            for (int mf = 0; mf < 2; mf++)
                ldsm4(a[mf], abase + mf * 16 * APB + (c * 64 + ks * 16) * 2);
#pragma unroll
            for (int nf = 0; nf < 8; nf++) {
                int nb = nw * 8 + nf;
                b[nf] = *(const uint2*)(wb + (((nb * 4 + ks) << 5) + lane) * 8);
            }
#pragma unroll
            for (int mf = 0; mf < 2; mf++)
#pragma unroll
                for (int nf = 0; nf < 8; nf++)
                    mma16(acc[mf][nf], a[mf], (const uint32_t*)&b[nf]);
        }
    }
}

// GEMM2: whole K=128 in one 32KB frag buffer, no internal barriers
__device__ __forceinline__ void gemm2(char* smc, uint32_t smbase,
                                      int mw, int nw, int lane,
                                      float acc[2][8][4]) {
    const uint32_t abase = a_addr(smbase, mw, lane);
#pragma unroll
    for (int ks8 = 0; ks8 < 8; ks8++) {
        const char* wb = smc + WB_B + (ks8 >> 2) * WB_CHB;
        int ks = ks8 & 3;
        uint32_t a[2][4];
        uint2    b[8];
#pragma unroll
        for (int mf = 0; mf < 2; mf++)
            ldsm4(a[mf], abase + mf * 16 * APB + (ks8 * 16) * 2);
#pragma unroll
        for (int nf = 0; nf < 8; nf++) {
            int nb = nw * 8 + nf;
            b[nf] = *(const uint2*)(wb + (((nb * 4 + ks) << 5) + lane) * 8);
        }
#pragma unroll
        for (int mf = 0; mf < 2; mf++)
#pragma unroll
            for (int nf = 0; nf < 8; nf++)
                mma16(acc[mf][nf], a[mf], (const uint32_t*)&b[nf]);
    }
}

// ------------------------- fused MLP kernel (edge / node) -------------------------
template <bool EDGE>
__global__ void __launch_bounds__(256, 2) mlp_mma_kernel(
    const float* __restrict__ w1full,   // original w1 (dist row, edge only)
    const float* __restrict__ b1, const float* __restrict__ b2,
    float* __restrict__ out, int M) {
    extern __shared__ char smc[];
    const uint32_t smbase = cvta_sh(smc);
    float* sB1  = (float*)(smc + B1_B);
    float* sB2  = (float*)(smc + B2_B);
    float* sW1l = (float*)(smc + W1L_B);
    float* sDst = (float*)(smc + DIST_B);
    int*   sRec = (int*)(smc + REC_B);
    int*   sSnd = (int*)(smc + SEND_B);

    const __half* gw1 = EDGE ? g_w1h : g_u1h;
    const __half* gw2 = EDGE ? g_w2h : g_u2h;

    const int tid  = threadIdx.x;
    const int lane = tid & 31;
    const int wid  = tid >> 5;
    const int mw   = wid >> 1;   // 0..3 (32-row block)
    const int nw   = wid & 1;    // 0..1 (64-col block)
    const int m0   = blockIdx.x * TMR;

    // w1 chunk 0 into flight immediately — overlaps bias loads + gather
    issueB1(gw1, 0, 0, smbase, tid);
    cp_commit();

    if (tid < 128) {
        sB1[tid] = b1[tid];
        sB2[tid] = b2[tid];
        if (EDGE) {
            sW1l[tid] = w1full[(size_t)256 * 128 + tid];
            int ge = m0 + tid;
            if (ge < M) {
                sSnd[tid] = g_send[ge];
                sRec[tid] = g_rec[ge];
                sDst[tid] = g_dist[ge];
            } else {
                sSnd[tid] = 0; sRec[tid] = -1; sDst[tid] = 0.0f;
            }
        }
    }
    __syncthreads();

    // gather state rows (LDG.128 -> STS.128): cols 0..127 from x16; 128..255
    // from x16 (edge) or aggr fp32->fp16 (node)
    const uint4* x16 = (const uint4*)g_x16;   // 16 uint4 per row
    for (int i = tid; i < TMR * 16; i += 256) {
        int r = i >> 4, c = i & 15;
        if (EDGE) {
            int s  = sSnd[r];
            int rc = sRec[r];
            if (rc < 0) rc = 0;
            uint4 vs = x16[(size_t)s * 16 + c];
            uint4 vr = x16[(size_t)rc * 16 + c];
            *(uint4*)(smc + r * APB + c * 16)       = vs;
            *(uint4*)(smc + r * APB + 256 + c * 16) = vr;
        } else {
            int gn = m0 + r;
            if (gn >= M) gn = M - 1;
            uint4 vx = x16[(size_t)gn * 16 + c];
            *(uint4*)(smc + r * APB + c * 16) = vx;
            const float4* ar = (const float4*)&g_aggr[(size_t)gn * HDIM + c * 8];
            float4 a0 = ar[0], a1 = ar[1];
            uint4 u;
            ((half2*)&u)[0] = __floats2half2_rn(a0.x, a0.y);
            ((half2*)&u)[1] = __floats2half2_rn(a0.z, a0.w);
            ((half2*)&u)[2] = __floats2half2_rn(a1.x, a1.y);
            ((half2*)&u)[3] = __floats2half2_rn(a1.z, a1.w);
            *(uint4*)(smc + r * APB + 256 + c * 16) = u;
        }
    }
    // (first gemm chunk's bar orders the gather)

    float acc[2][8][4];
#pragma unroll
    for (int mf = 0; mf < 2; mf++)
#pragma unroll
        for (int nf = 0; nf < 8; nf++)
#pragma unroll
            for (int g = 0; g < 4; g++) acc[mf][nf][g] = 0.0f;

    // GEMM1: K=256 (4 chunks of 64)
    gemm1(gw1, smc, smbase, mw, nw, lane, tid, acc);
    __syncthreads();   // all chunk-3 reads (sA + WB) done

    // prefetch ALL of w2 (32KB) while we do epilogue math
    issueW2(gw2, smbase, tid);
    cp_commit();

    // epilogue 1: h = silu(acc + b1 [+ dist*w1_last]) -> fp16 -> A cols 0..127
#pragma unroll
    for (int mf = 0; mf < 2; mf++) {
        int r0 = mw * 32 + mf * 16 + (lane >> 2);
        int r1 = r0 + 8;
        float d0 = EDGE ? sDst[r0] : 0.0f;
        float d1 = EDGE ? sDst[r1] : 0.0f;
#pragma unroll
        for (int nf = 0; nf < 8; nf++) {
            int c0 = nw * 64 + nf * 8 + (lane & 3) * 2;
            float* v = acc[mf][nf];
            float wl0 = EDGE ? sW1l[c0] : 0.0f;
            float wl1 = EDGE ? sW1l[c0 + 1] : 0.0f;
            float h00 = silu_f(v[0] + sB1[c0]     + d0 * wl0);
            float h01 = silu_f(v[1] + sB1[c0 + 1] + d0 * wl1);
            float h10 = silu_f(v[2] + sB1[c0]     + d1 * wl0);
            float h11 = silu_f(v[3] + sB1[c0 + 1] + d1 * wl1);
            *(half2*)(smc + r0 * APB + c0 * 2) = __floats2half2_rn(h00, h01);
            *(half2*)(smc + r1 * APB + c0 * 2) = __floats2half2_rn(h10, h11);
            v[0] = v[1] = v[2] = v[3] = 0.0f;
        }
    }
    cp_wait<0>();
    __syncthreads();   // w2 + h tiles visible to all

    // GEMM2: K=128, un-barriered
    gemm2(smc, smbase, mw, nw, lane, acc);
    __syncthreads();   // all A reads done before fp32 overlay

    // epilogue 2: stage fp32 result over the A tile region (h is dead now)
#pragma unroll
    for (int mf = 0; mf < 2; mf++) {
        int r0 = mw * 32 + mf * 16 + (lane >> 2);
        int r1 = r0 + 8;
#pragma unroll
        for (int nf = 0; nf < 8; nf++) {
            int c0 = nw * 64 + nf * 8 + (lane & 3) * 2;
            float* v = acc[mf][nf];
            float o00 = v[0] + sB2[c0];
            float o01 = v[1] + sB2[c0 + 1];
            float o10 = v[2] + sB2[c0];
            float o11 = v[3] + sB2[c0 + 1];
            if (EDGE) {
                o00 = silu_f(o00); o01 = silu_f(o01);
                o10 = silu_f(o10); o11 = silu_f(o11);
            }
            *(float2*)(smc + r0 * APB + c0 * 4) = make_float2(o00, o01);
            *(float2*)(smc + r1 * APB + c0 * 4) = make_float2(o10, o11);
        }
    }
    __syncthreads();

    // writeout: 128 rows x 2 halves, scatter-add or store
    {
        int r = tid >> 1, half = tid & 1;
        const float4* src = (const float4*)(smc + r * APB + half * 256);
        if (EDGE) {
            int rc = sRec[r];
            if (rc >= 0) {
                float* dst = &g_aggr[(size_t)rc * HDIM + half * 64];
#pragma unroll
                for (int j = 0; j < 16; j++) {
                    float4 v = src[j];
                    red4(dst + j * 4, v.x, v.y, v.z, v.w);
                }
            }
        } else {
            int gn = m0 + r;
            if (gn < M) {
                float4* dst = (float4*)&out[(size_t)gn * HDIM + half * 64];
#pragma unroll
                for (int j = 0; j < 16; j++) dst[j] = src[j];
            }
        }
    }
}

// ------------------------- launch -------------------------
extern "C" void kernel_launch(void* const* d_in, const int* in_sizes, int n_in,
                              void* d_out, int out_size) {
    const float* x   = (const float*)d_in[0];
    const float* pos = (const float*)d_in[1];
    const int*   ei  = (const int*)d_in[2];
    const float* mw1 = (const float*)d_in[3];
    const float* mb1 = (const float*)d_in[4];
    const float* mw2 = (const float*)d_in[5];
    const float* mb2 = (const float*)d_in[6];
    const float* uw1 = (const float*)d_in[7];
    const float* ub1 = (const float*)d_in[8];
    const float* uw2 = (const float*)d_in[9];
    const float* ub2 = (const float*)d_in[10];

    int N = in_sizes[0] / HDIM;
    int E = in_sizes[2] / 2;

    cudaFuncSetAttribute(mlp_mma_kernel<true>,
                         cudaFuncAttributeMaxDynamicSharedMemorySize, SMEM_BYTES);
    cudaFuncSetAttribute(mlp_mma_kernel<false>,
                         cudaFuncAttributeMaxDynamicSharedMemorySize, SMEM_BYTES);

    // zero aggr at HBM rate (async memset, graph-capturable, no alloc)
    void* aggr_ptr = nullptr;
    cudaGetSymbolAddress(&aggr_ptr, g_aggr);
    cudaMemsetAsync(aggr_ptr, 0, (size_t)N * HDIM * sizeof(float));

    prep_all<<<2048, 256>>>(ei, pos, x, mw1, mw2, uw1, uw2, N, E);
    mlp_mma_kernel<true><<<(E + TMR - 1) / TMR, 256, SMEM_BYTES>>>(
        mw1, mb1, mb2, nullptr, E);
    mlp_mma_kernel<false><<<(N + TMR - 1) / TMR, 256, SMEM_BYTES>>>(
        uw1, ub1, ub2, (float*)d_out, N);
}

// round 17
// speedup vs baseline: 1.3683x; 1.0236x over previous
#include <cuda_runtime.h>
#include <cuda_fp16.h>
#include <math.h>
#include <stdint.h>

#define HDIM 128
#define MAXN 50000
#define MAXE 640000
#define TMR  128                    // rows per CTA tile

// byte-offset shared layout
#define APB     528                 // A row pitch bytes (264 halves)
#define WB_B    (TMR * APB)         // 67584
#define WB_CHB  16384               // one 64k x 128n fp16 chunk, frag-ordered
#define B1_B    (WB_B + 2 * WB_CHB) // 100352
#define B2_B    (B1_B + 512)
#define W1L_B   (B2_B + 512)
#define DIST_B  (W1L_B + 512)
#define REC_B   (DIST_B + 512)
#define SEND_B  (REC_B + 512)
#define SMEM_BYTES (SEND_B + 512)   // 103424 -> 2 CTAs/SM

// ------------------------- device scratch -------------------------
__device__ __align__(16) float  g_aggr[(size_t)MAXN * HDIM];
__device__ __align__(16) float  g_pq[(size_t)MAXN * 256];   // [P | Q+b1] per node
__device__ __align__(16) __half g_x16[(size_t)MAXN * HDIM];
__device__ int   g_send[MAXE];
__device__ int   g_rec[MAXE];
__device__ float g_dist[MAXE];
// frag-ordered fp16 weights: [kchunk64][nb*4+ks][lane][reg] packed as halves
__device__ __align__(16) __half g_w1h[4 * 8192];   // edge w1, K=256 (chunks 0-1=W1a, 2-3=W1b)
__device__ __align__(16) __half g_w2h[2 * 8192];   // edge w2, K=128
__device__ __align__(16) __half g_u1h[4 * 8192];   // node w1, K=256
__device__ __align__(16) __half g_u2h[2 * 8192];   // node w2, K=128

// ------------------------- helpers -------------------------
__device__ __forceinline__ float silu_f(float v) {
    float t;
    asm("tanh.approx.f32 %0, %1;" : "=f"(t) : "f"(0.5f * v));
    return 0.5f * v * (1.0f + t);
}
__device__ __forceinline__ uint32_t cvta_sh(const void* p) {
    uint32_t a;
    asm("{ .reg .u64 t; cvta.to.shared.u64 t, %1; cvt.u32.u64 %0, t; }"
        : "=r"(a) : "l"(p));
    return a;
}
__device__ __forceinline__ void mma16(float d[4], const uint32_t a[4],
                                      const uint32_t b[2]) {
    asm volatile(
        "mma.sync.aligned.m16n8k16.row.col.f32.f16.f16.f32 "
        "{%0,%1,%2,%3},{%4,%5,%6,%7},{%8,%9},{%0,%1,%2,%3};"
        : "+f"(d[0]), "+f"(d[1]), "+f"(d[2]), "+f"(d[3])
        : "r"(a[0]), "r"(a[1]), "r"(a[2]), "r"(a[3]), "r"(b[0]), "r"(b[1]));
}
__device__ __forceinline__ void ldsm4(uint32_t r[4], uint32_t addr) {
    asm volatile("ldmatrix.sync.aligned.m8n8.x4.shared.b16 {%0,%1,%2,%3}, [%4];"
                 : "=r"(r[0]), "=r"(r[1]), "=r"(r[2]), "=r"(r[3]) : "r"(addr));
}
__device__ __forceinline__ void red4(float* p, float a, float b, float c, float d) {
    asm volatile("red.global.add.v4.f32 [%0], {%1,%2,%3,%4};"
                 :: "l"(p), "f"(a), "f"(b), "f"(c), "f"(d) : "memory");
}
__device__ __forceinline__ void cp16(uint32_t dst_sh, const void* src) {
    asm volatile("cp.async.ca.shared.global [%0], [%1], 16;"
                 :: "r"(dst_sh), "l"(src) : "memory");
}
__device__ __forceinline__ void cp_commit() {
    asm volatile("cp.async.commit_group;" ::: "memory");
}
template <int W>
__device__ __forceinline__ void cp_wait() {
    asm volatile("cp.async.wait_group %0;" :: "n"(W) : "memory");
}

// frag-order half-index; word = chunkbase + (nb*4+ks)*64 + lane*2 + reg
__device__ __forceinline__ int fragh(int n, int k) {
    int kc   = k >> 6;
    int ks   = (k >> 4) & 3;
    int reg  = (k >> 3) & 1;
    int lane = (n & 7) * 4 + ((k >> 1) & 3);
    int idx32 = kc * 4096 + (((n >> 3) * 4 + ks) << 6) + lane * 2 + reg;
    return idx32 * 2 + (k & 1);
}

// ------------------------- fused prep kernel (aggr zeroed by memset) ---------
__global__ void prep_all(const int* __restrict__ ei32,
                         const float* __restrict__ pos,
                         const float* __restrict__ x,
                         const float* __restrict__ mw1, const float* __restrict__ mw2,
                         const float* __restrict__ uw1, const float* __restrict__ uw2,
                         int N, int E) {
    bool is64 = true;
#pragma unroll
    for (int t = 0; t < 16; t++) is64 &= (ei32[2 * t + 1] == 0);

    const long long NH  = (long long)N * HDIM;
    const long long NX8 = NH >> 3;
    const long long t1 = NX8;
    const long long t2 = t1 + E;
    const long long t3 = t2 + 32768;
    const long long t4 = t3 + 16384;
    const long long t5 = t4 + 32768;
    const long long t6 = t5 + 16384;

    long long i = (long long)blockIdx.x * blockDim.x + threadIdx.x;
    long long st = (long long)gridDim.x * blockDim.x;
    for (; i < t6; i += st) {
        if (i < t1) {
            long long j = i << 3;
            float4 a0 = *(const float4*)(x + j);
            float4 a1 = *(const float4*)(x + j + 4);
            uint4 u;
            ((half2*)&u)[0] = __floats2half2_rn(a0.x, a0.y);
            ((half2*)&u)[1] = __floats2half2_rn(a0.z, a0.w);
            ((half2*)&u)[2] = __floats2half2_rn(a1.x, a1.y);
            ((half2*)&u)[3] = __floats2half2_rn(a1.z, a1.w);
            *(uint4*)(g_x16 + j) = u;
        } else if (i < t2) {
            int e = (int)(i - t1);
            int s, r;
            if (is64) { s = ei32[2 * (size_t)e]; r = ei32[2 * ((size_t)E + e)]; }
            else      { s = ei32[e];             r = ei32[(size_t)E + e]; }
            s = min(max(s, 0), N - 1);
            r = min(max(r, 0), N - 1);
            g_send[e] = s;
            g_rec[e]  = r;
            float dx = pos[s * 3 + 0] - pos[r * 3 + 0];
            float dy = pos[s * 3 + 1] - pos[r * 3 + 1];
            float dz = pos[s * 3 + 2] - pos[r * 3 + 2];
            g_dist[e] = sqrtf(dx * dx + dy * dy + dz * dz);
        } else if (i < t3) {
            int j = (int)(i - t2);
            int n = j >> 8, k = j & 255;
            g_w1h[fragh(n, k)] = __float2half_rn(mw1[k * 128 + n]);
        } else if (i < t4) {
            int j = (int)(i - t3);
            int n = j >> 7, k = j & 127;
            g_w2h[fragh(n, k)] = __float2half_rn(mw2[k * 128 + n]);
        } else if (i < t5) {
            int j = (int)(i - t4);
            int n = j >> 8, k = j & 255;
            g_u1h[fragh(n, k)] = __float2half_rn(uw1[k * 128 + n]);
        } else {
            int j = (int)(i - t5);
            int n = j >> 7, k = j & 127;
            g_u2h[fragh(n, k)] = __float2half_rn(uw2[k * 128 + n]);
        }
    }
}

// ------------------------- fp16 mma GEMM building blocks --------------------
__device__ __forceinline__ void issueB1(const __half* __restrict__ gB, int c,
                                        int buf, uint32_t smbase, int tid) {
#pragma unroll
    for (int it = 0; it < 4; it++) {
        int idx = (tid + it * 256) * 16;
        cp16(smbase + WB_B + buf * WB_CHB + idx, (const char*)gB + c * WB_CHB + idx);
    }
}
__device__ __forceinline__ void issueW2(const __half* __restrict__ gB,
                                        uint32_t smbase, int tid) {
#pragma unroll
    for (int it = 0; it < 8; it++) {
        int idx = (tid + it * 256) * 16;
        cp16(smbase + WB_B + idx, (const char*)gB + idx);
    }
}

__device__ __forceinline__ uint32_t a_addr(uint32_t smbase, int mw, int lane) {
    int row  = mw * 32 + (lane & 7) + ((lane >> 3) & 1) * 8;
    int koff = (lane >> 4) * 8;           // halves
    return smbase + row * APB + koff * 2;
}

// one 64-wide K-chunk of mma into acc (A col base = ck*64)
__device__ __forceinline__ void mma_chunk(char* smc, uint32_t abase, int ck,
                                          int buf, int nw, int lane,
                                          float acc[2][8][4]) {
    const char* wb = smc + WB_B + buf * WB_CHB;
#pragma unroll
    for (int ks = 0; ks < 4; ks++) {
        uint32_t a[2][4];
        uint2    b[8];
#pragma unroll
        for (int mf = 0; mf < 2; mf++)
            ldsm4(a[mf], abase + mf * 16 * APB + (ck * 64 + ks * 16) * 2);
#pragma unroll
        for (int nf = 0; nf < 8; nf++) {
            int nb = nw * 8 + nf;
            b[nf] = *(const uint2*)(wb + (((nb * 4 + ks) << 5) + lane) * 8);
        }
#pragma unroll
        for (int mf = 0; mf < 2; mf++)
#pragma unroll
            for (int nf = 0; nf < 8; nf++)
                mma16(acc[mf][nf], a[mf], (const uint32_t*)&b[nf]);
    }
}

// full GEMM1-style loop (4 chunks, single bar per chunk; chunk0 pre-issued)
__device__ __forceinline__ void gemm1(const __half* __restrict__ gB,
                                      char* smc, uint32_t smbase,
                                      int mw, int nw, int lane, int tid,
                                      float acc[2][8][4]) {
    const uint32_t abase = a_addr(smbase, mw, lane);
    for (int c = 0; c < 4; c++) {
        cp_wait<0>();
        __syncthreads();
        if (c + 1 < 4) { issueB1(gB, c + 1, (c + 1) & 1, smbase, tid); cp_commit(); }
        mma_chunk(smc, abase, c, c & 1, nw, lane, acc);
    }
}

// GEMM2: whole K=128 in one 32KB frag buffer, no internal barriers
__device__ __forceinline__ void gemm2(char* smc, uint32_t smbase,
                                      int mw, int nw, int lane,
                                      float acc[2][8][4]) {
    const uint32_t abase = a_addr(smbase, mw, lane);
#pragma unroll
    for (int ks8 = 0; ks8 < 8; ks8++) {
        const char* wb = smc + WB_B + (ks8 >> 2) * WB_CHB;
        int ks = ks8 & 3;
        uint32_t a[2][4];
        uint2    b[8];
#pragma unroll
        for (int mf = 0; mf < 2; mf++)
            ldsm4(a[mf], abase + mf * 16 * APB + (ks8 * 16) * 2);
#pragma unroll
        for (int nf = 0; nf < 8; nf++) {
            int nb = nw * 8 + nf;
            b[nf] = *(const uint2*)(wb + (((nb * 4 + ks) << 5) + lane) * 8);
        }
#pragma unroll
        for (int mf = 0; mf < 2; mf++)
#pragma unroll
            for (int nf = 0; nf < 8; nf++)
                mma16(acc[mf][nf], a[mf], (const uint32_t*)&b[nf]);
    }
}

// ------------------------- PQ precompute: P=x@W1a, Q=x@W1b+b1 ----------------
__global__ void __launch_bounds__(256, 2) pq_kernel(
    const float* __restrict__ b1, int N) {
    extern __shared__ char smc[];
    const uint32_t smbase = cvta_sh(smc);
    float* sB1 = (float*)(smc + B1_B);

    const int tid  = threadIdx.x;
    const int lane = tid & 31;
    const int wid  = tid >> 5;
    const int mw   = wid >> 1;
    const int nw   = wid & 1;
    const int m0   = blockIdx.x * TMR;

    issueB1(g_w1h, 0, 0, smbase, tid);
    cp_commit();

    if (tid < 128) sB1[tid] = b1[tid];

    // gather x rows into BOTH A halves (cols 0..127 and 128..255)
    const uint4* x16 = (const uint4*)g_x16;
    for (int i = tid; i < TMR * 16; i += 256) {
        int r = i >> 4, c = i & 15;
        int gn = m0 + r;
        if (gn >= N) gn = N - 1;
        uint4 v = x16[(size_t)gn * 16 + c];
        *(uint4*)(smc + r * APB + c * 16)       = v;
        *(uint4*)(smc + r * APB + 256 + c * 16) = v;
    }

    float acc[2][8][4];
#pragma unroll
    for (int mf = 0; mf < 2; mf++)
#pragma unroll
        for (int nf = 0; nf < 8; nf++)
#pragma unroll
            for (int g = 0; g < 4; g++) acc[mf][nf][g] = 0.0f;

    const uint32_t abase = a_addr(smbase, mw, lane);
    for (int c = 0; c < 4; c++) {
        cp_wait<0>();
        __syncthreads();
        if (c + 1 < 4) { issueB1(g_w1h, c + 1, (c + 1) & 1, smbase, tid); cp_commit(); }
        mma_chunk(smc, abase, c, c & 1, nw, lane, acc);
        if (c == 1) {
            // store P, reset acc
#pragma unroll
            for (int mf = 0; mf < 2; mf++) {
                int r0 = mw * 32 + mf * 16 + (lane >> 2);
                int r1 = r0 + 8;
#pragma unroll
                for (int nf = 0; nf < 8; nf++) {
                    int c0 = nw * 64 + nf * 8 + (lane & 3) * 2;
                    float* v = acc[mf][nf];
                    if (m0 + r0 < N)
                        *(float2*)&g_pq[(size_t)(m0 + r0) * 256 + c0] =
                            make_float2(v[0], v[1]);
                    if (m0 + r1 < N)
                        *(float2*)&g_pq[(size_t)(m0 + r1) * 256 + c0] =
                            make_float2(v[2], v[3]);
                    v[0] = v[1] = v[2] = v[3] = 0.0f;
                }
            }
        }
    }
    // store Q + b1
#pragma unroll
    for (int mf = 0; mf < 2; mf++) {
        int r0 = mw * 32 + mf * 16 + (lane >> 2);
        int r1 = r0 + 8;
#pragma unroll
        for (int nf = 0; nf < 8; nf++) {
            int c0 = nw * 64 + nf * 8 + (lane & 3) * 2;
            float* v = acc[mf][nf];
            float b0 = sB1[c0], bb1 = sB1[c0 + 1];
            if (m0 + r0 < N)
                *(float2*)&g_pq[(size_t)(m0 + r0) * 256 + 128 + c0] =
                    make_float2(v[0] + b0, v[1] + bb1);
            if (m0 + r1 < N)
                *(float2*)&g_pq[(size_t)(m0 + r1) * 256 + 128 + c0] =
                    make_float2(v[2] + b0, v[3] + bb1);
        }
    }
}

// ------------------------- edge kernel: h=silu(P[s]+Q[r]+d*w1l), GEMM2, scatter
__global__ void __launch_bounds__(256, 2) edge_kernel(
    const float* __restrict__ w1full, const float* __restrict__ b2, int E) {
    extern __shared__ char smc[];
    const uint32_t smbase = cvta_sh(smc);
    float* sB2  = (float*)(smc + B2_B);
    float* sW1l = (float*)(smc + W1L_B);
    float* sDst = (float*)(smc + DIST_B);
    int*   sRec = (int*)(smc + REC_B);
    int*   sSnd = (int*)(smc + SEND_B);

    const int tid  = threadIdx.x;
    const int lane = tid & 31;
    const int wid  = tid >> 5;
    const int mw   = wid >> 1;
    const int nw   = wid & 1;
    const int m0   = blockIdx.x * TMR;

    // entire w2 (32KB) into flight immediately
    issueW2(g_w2h, smbase, tid);
    cp_commit();

    if (tid < 128) {
        sB2[tid]  = b2[tid];
        sW1l[tid] = w1full[(size_t)256 * 128 + tid];
        int ge = m0 + tid;
        if (ge < E) {
            sSnd[tid] = g_send[ge];
            sRec[tid] = g_rec[ge];
            sDst[tid] = g_dist[ge];
        } else {
            sSnd[tid] = 0; sRec[tid] = -1; sDst[tid] = 0.0f;
        }
    }
    __syncthreads();

    // gather-compute h -> fp16 A cols 0..127
    for (int i = tid; i < TMR * 32; i += 256) {
        int r = i >> 5, c4 = i & 31;           // c4: float4 index (0..31)
        int s  = sSnd[r];
        int rc = sRec[r];
        if (rc < 0) rc = 0;
        float d = sDst[r];
        float4 p = *(const float4*)&g_pq[(size_t)s * 256 + c4 * 4];
        float4 q = *(const float4*)&g_pq[(size_t)rc * 256 + 128 + c4 * 4];
        int cb = c4 * 4;
        float h0 = silu_f(p.x + q.x + d * sW1l[cb + 0]);
        float h1 = silu_f(p.y + q.y + d * sW1l[cb + 1]);
        float h2 = silu_f(p.z + q.z + d * sW1l[cb + 2]);
        float h3 = silu_f(p.w + q.w + d * sW1l[cb + 3]);
        uint2 u;
        ((half2*)&u)[0] = __floats2half2_rn(h0, h1);
        ((half2*)&u)[1] = __floats2half2_rn(h2, h3);
        *(uint2*)(smc + r * APB + c4 * 8) = u;
    }
    cp_wait<0>();
    __syncthreads();   // w2 + h tiles visible

    float acc[2][8][4];
#pragma unroll
    for (int mf = 0; mf < 2; mf++)
#pragma unroll
        for (int nf = 0; nf < 8; nf++)
#pragma unroll
            for (int g = 0; g < 4; g++) acc[mf][nf][g] = 0.0f;

    gemm2(smc, smbase, mw, nw, lane, acc);
    __syncthreads();   // A reads done before fp32 overlay

    // epilogue: msg = silu(acc + b2), stage fp32 over A region
#pragma unroll
    for (int mf = 0; mf < 2; mf++) {
        int r0 = mw * 32 + mf * 16 + (lane >> 2);
        int r1 = r0 + 8;
#pragma unroll
        for (int nf = 0; nf < 8; nf++) {
            int c0 = nw * 64 + nf * 8 + (lane & 3) * 2;
            float* v = acc[mf][nf];
            float o00 = silu_f(v[0] + sB2[c0]);
            float o01 = silu_f(v[1] + sB2[c0 + 1]);
            float o10 = silu_f(v[2] + sB2[c0]);
            float o11 = silu_f(v[3] + sB2[c0 + 1]);
            *(float2*)(smc + r0 * APB + c0 * 4) = make_float2(o00, o01);
            *(float2*)(smc + r1 * APB + c0 * 4) = make_float2(o10, o11);
        }
    }
    __syncthreads();

    // writeout: row-coalesced scatter-add
    {
        int r = tid >> 1, half = tid & 1;
        const float4* src = (const float4*)(smc + r * APB + half * 256);
        int rc = sRec[r];
        if (rc >= 0) {
            float* dst = &g_aggr[(size_t)rc * HDIM + half * 64];
#pragma unroll
            for (int j = 0; j < 16; j++) {
                float4 v = src[j];
                red4(dst + j * 4, v.x, v.y, v.z, v.w);
            }
        }
    }
}

// ------------------------- node kernel (unchanged R16 path) ------------------
__global__ void __launch_bounds__(256, 2) node_kernel(
    const float* __restrict__ b1, const float* __restrict__ b2,
    float* __restrict__ out, int M) {
    extern __shared__ char smc[];
    const uint32_t smbase = cvta_sh(smc);
    float* sB1 = (float*)(smc + B1_B);
    float* sB2 = (float*)(smc + B2_B);

    const int tid  = threadIdx.x;
    const int lane = tid & 31;
    const int wid  = tid >> 5;
    const int mw   = wid >> 1;
    const int nw   = wid & 1;
    const int m0   = blockIdx.x * TMR;

    issueB1(g_u1h, 0, 0, smbase, tid);
    cp_commit();

    if (tid < 128) { sB1[tid] = b1[tid]; sB2[tid] = b2[tid]; }
    __syncthreads();

    const uint4* x16 = (const uint4*)g_x16;
    for (int i = tid; i < TMR * 16; i += 256) {
        int r = i >> 4, c = i & 15;
        int gn = m0 + r;
        if (gn >= M) gn = M - 1;
        uint4 vx = x16[(size_t)gn * 16 + c];
        *(uint4*)(smc + r * APB + c * 16) = vx;
        const float4* ar = (const float4*)&g_aggr[(size_t)gn * HDIM + c * 8];
        float4 a0 = ar[0], a1 = ar[1];
        uint4 u;
        ((half2*)&u)[0] = __floats2half2_rn(a0.x, a0.y);
        ((half2*)&u)[1] = __floats2half2_rn(a0.z, a0.w);
        ((half2*)&u)[2] = __floats2half2_rn(a1.x, a1.y);
        ((half2*)&u)[3] = __floats2half2_rn(a1.z, a1.w);
        *(uint4*)(smc + r * APB + 256 + c * 16) = u;
    }

    float acc[2][8][4];
#pragma unroll
    for (int mf = 0; mf < 2; mf++)
#pragma unroll
        for (int nf = 0; nf < 8; nf++)
#pragma unroll
            for (int g = 0; g < 4; g++) acc[mf][nf][g] = 0.0f;

    gemm1(g_u1h, smc, smbase, mw, nw, lane, tid, acc);
    __syncthreads();

    issueW2(g_u2h, smbase, tid);
    cp_commit();

#pragma unroll
    for (int mf = 0; mf < 2; mf++) {
        int r0 = mw * 32 + mf * 16 + (lane >> 2);
        int r1 = r0 + 8;
#pragma unroll
        for (int nf = 0; nf < 8; nf++) {
            int c0 = nw * 64 + nf * 8 + (lane & 3) * 2;
            float* v = acc[mf][nf];
            float h00 = silu_f(v[0] + sB1[c0]);
            float h01 = silu_f(v[1] + sB1[c0 + 1]);
            float h10 = silu_f(v[2] + sB1[c0]);
            float h11 = silu_f(v[3] + sB1[c0 + 1]);
            *(half2*)(smc + r0 * APB + c0 * 2) = __floats2half2_rn(h00, h01);
            *(half2*)(smc + r1 * APB + c0 * 2) = __floats2half2_rn(h10, h11);
            v[0] = v[1] = v[2] = v[3] = 0.0f;
        }
    }
    cp_wait<0>();
    __syncthreads();

    gemm2(smc, smbase, mw, nw, lane, acc);
    __syncthreads();

#pragma unroll
    for (int mf = 0; mf < 2; mf++) {
        int r0 = mw * 32 + mf * 16 + (lane >> 2);
        int r1 = r0 + 8;
#pragma unroll
        for (int nf = 0; nf < 8; nf++) {
            int c0 = nw * 64 + nf * 8 + (lane & 3) * 2;
            float* v = acc[mf][nf];
            *(float2*)(smc + r0 * APB + c0 * 4) =
                make_float2(v[0] + sB2[c0], v[1] + sB2[c0 + 1]);
            *(float2*)(smc + r1 * APB + c0 * 4) =
                make_float2(v[2] + sB2[c0], v[3] + sB2[c0 + 1]);
        }
    }
    __syncthreads();

    {
        int r = tid >> 1, half = tid & 1;
        const float4* src = (const float4*)(smc + r * APB + half * 256);
        int gn = m0 + r;
        if (gn < M) {
            float4* dst = (float4*)&out[(size_t)gn * HDIM + half * 64];
#pragma unroll
            for (int j = 0; j < 16; j++) dst[j] = src[j];
        }
    }
}

// ------------------------- launch -------------------------
extern "C" void kernel_launch(void* const* d_in, const int* in_sizes, int n_in,
                              void* d_out, int out_size) {
    const float* x   = (const float*)d_in[0];
    const float* pos = (const float*)d_in[1];
    const int*   ei  = (const int*)d_in[2];
    const float* mw1 = (const float*)d_in[3];
    const float* mb1 = (const float*)d_in[4];
    const float* mw2 = (const float*)d_in[5];
    const float* mb2 = (const float*)d_in[6];
    const float* uw1 = (const float*)d_in[7];
    const float* ub1 = (const float*)d_in[8];
    const float* uw2 = (const float*)d_in[9];
    const float* ub2 = (const float*)d_in[10];

    int N = in_sizes[0] / HDIM;
    int E = in_sizes[2] / 2;

    cudaFuncSetAttribute(pq_kernel, cudaFuncAttributeMaxDynamicSharedMemorySize,
                         SMEM_BYTES);
    cudaFuncSetAttribute(edge_kernel, cudaFuncAttributeMaxDynamicSharedMemorySize,
                         SMEM_BYTES);
    cudaFuncSetAttribute(node_kernel, cudaFuncAttributeMaxDynamicSharedMemorySize,
                         SMEM_BYTES);

    void* aggr_ptr = nullptr;
    cudaGetSymbolAddress(&aggr_ptr, g_aggr);
    cudaMemsetAsync(aggr_ptr, 0, (size_t)N * HDIM * sizeof(float));

    prep_all<<<2048, 256>>>(ei, pos, x, mw1, mw2, uw1, uw2, N, E);
    pq_kernel<<<(N + TMR - 1) / TMR, 256, SMEM_BYTES>>>(mb1, N);
    edge_kernel<<<(E + TMR - 1) / TMR, 256, SMEM_BYTES>>>(mw1, mb2, E);
    node_kernel<<<(N + TMR - 1) / TMR, 256, SMEM_BYTES>>>(
        ub1, ub2, (float*)d_out, N);
}